// round 1
// baseline (speedup 1.0000x reference)
#include <cuda_runtime.h>
#include <math.h>

// ---------------- problem constants ----------------
#define Bb   2
#define Ss   1024
#define Dd   1024
#define Hh   16
#define HDd  64
#define MMm  16
#define WWw  8
#define RMm  8
#define CRc  8
#define FFD  4096
#define ROWS (Bb*Ss)          // 2048

// ---------------- scratch (no allocations allowed) ----------------
__device__ float g_v   [Bb*Ss*Dd];
__device__ float g_pp  [4*Bb*Dd];
__device__ float g_pool[Bb*Dd];
__device__ float g_wts [Bb*Hh*MMm];
__device__ float g_ckr [Bb*Hh*Ss];
__device__ float g_qm  [Bb*Ss*Hh];
__device__ float g_km  [Bb*Ss*Hh];
__device__ float g_qc  [Bb*Ss*Hh*CRc];
__device__ float g_kc  [Bb*Ss*Hh*CRc];
__device__ float g_ctx [Bb*Ss*Dd];
__device__ float g_ao  [Bb*Ss*Dd];
__device__ float g_h   [Bb*Ss*Dd];
__device__ float g_ffn [Bb*Ss*FFD];
__device__ float g_f2  [Bb*Ss*Dd];

// ---------------- generic tiled fp32 GEMM: C = A[M,K] @ B[K,N] + bias, opt GELU ----------------
#define BM 128
#define BN 64
#define BK 16

template<bool GELU>
__global__ void __launch_bounds__(256) gemm_k(const float* __restrict__ A,
                                              const float* __restrict__ Bm,
                                              const float* __restrict__ bias,
                                              float* __restrict__ C,
                                              int Mr, int N, int K)
{
    __shared__ float As[BK][BM + 4];
    __shared__ float Bs[BK][BN + 4];
    const int tid = threadIdx.x;
    const int tx = tid & 15;          // N direction, 4 cols each
    const int ty = tid >> 4;          // M direction, 8 rows each
    const int m0 = blockIdx.y * BM;
    const int n0 = blockIdx.x * BN;

    const int ar  = tid >> 2;         // 0..63  (A tile row within group)
    const int ac  = (tid & 3) * 4;    // 0,4,8,12 (A tile col, float4)
    const int bkr = tid >> 4;         // 0..15
    const int bnc = (tid & 15) * 4;   // 0..60

    float acc[8][4];
    #pragma unroll
    for (int i = 0; i < 8; i++)
        #pragma unroll
        for (int j = 0; j < 4; j++) acc[i][j] = 0.f;

    for (int k0 = 0; k0 < K; k0 += BK) {
        float4 a0 = make_float4(0,0,0,0), a1 = make_float4(0,0,0,0), bv = make_float4(0,0,0,0);
        {
            int r0 = m0 + ar;
            if (r0 < Mr)       a0 = *(const float4*)(A + (size_t)r0*K + k0 + ac);
            int r1 = m0 + ar + 64;
            if (r1 < Mr)       a1 = *(const float4*)(A + (size_t)r1*K + k0 + ac);
            if (n0 + bnc < N)  bv = *(const float4*)(Bm + (size_t)(k0 + bkr)*N + n0 + bnc);
        }
        __syncthreads();
        As[ac+0][ar]    = a0.x; As[ac+1][ar]    = a0.y; As[ac+2][ar]    = a0.z; As[ac+3][ar]    = a0.w;
        As[ac+0][ar+64] = a1.x; As[ac+1][ar+64] = a1.y; As[ac+2][ar+64] = a1.z; As[ac+3][ar+64] = a1.w;
        *(float4*)&Bs[bkr][bnc] = bv;
        __syncthreads();

        #pragma unroll
        for (int kk = 0; kk < BK; kk++) {
            float4 av0 = *(const float4*)&As[kk][ty*8];
            float4 av1 = *(const float4*)&As[kk][ty*8 + 4];
            float4 b4  = *(const float4*)&Bs[kk][tx*4];
            float am[8] = {av0.x,av0.y,av0.z,av0.w,av1.x,av1.y,av1.z,av1.w};
            float bn[4] = {b4.x,b4.y,b4.z,b4.w};
            #pragma unroll
            for (int i = 0; i < 8; i++)
                #pragma unroll
                for (int j = 0; j < 4; j++)
                    acc[i][j] += am[i] * bn[j];
        }
    }

    #pragma unroll
    for (int i = 0; i < 8; i++) {
        int row = m0 + ty*8 + i;
        if (row >= Mr) continue;
        #pragma unroll
        for (int j = 0; j < 4; j++) {
            int col = n0 + tx*4 + j;
            if (col >= N) continue;
            float v = acc[i][j] + (bias ? bias[col] : 0.f);
            if (GELU) v = 0.5f * v * (1.f + erff(v * 0.70710678118654752f));
            C[(size_t)row*N + col] = v;
        }
    }
}

// ---------------- pooled mean over S (two stage, deterministic) ----------------
__global__ void pool1_k(const float* __restrict__ x, float* __restrict__ pp)
{
    int idx = blockIdx.x * 256 + threadIdx.x;       // 0..2047 over (b,d)
    int sl  = blockIdx.y;                           // 0..3
    int b = idx >> 10, d = idx & 1023;
    const float* xp = x + (size_t)(b*Ss + sl*256)*Dd + d;
    float s0=0,s1=0,s2=0,s3=0;
    for (int q = 0; q < 256; q += 4) {
        s0 += xp[(size_t)(q+0)*Dd];
        s1 += xp[(size_t)(q+1)*Dd];
        s2 += xp[(size_t)(q+2)*Dd];
        s3 += xp[(size_t)(q+3)*Dd];
    }
    pp[sl*2048 + idx] = (s0+s1)+(s2+s3);
}

__global__ void pool2_k(const float* __restrict__ pp, float* __restrict__ pooled)
{
    int idx = blockIdx.x * 256 + threadIdx.x;
    pooled[idx] = (pp[idx] + pp[2048+idx] + pp[4096+idx] + pp[6144+idx]) * (1.f/Ss);
}

// ---------------- gating: gl/mod dots + low-rank modulation + softmax ----------------
// NOTE: straight-through top-k is identity in forward => wts = softmax(gl)
__global__ void __launch_bounds__(256) gating_k(const float* __restrict__ pooled,
    const float* __restrict__ gate_w, const float* __restrict__ gate_b,
    const float* __restrict__ mod_w,  const float* __restrict__ mod_b,
    const float* __restrict__ mod_basis, float* __restrict__ wts)
{
    int blk = blockIdx.x;
    int b = blk / Hh, h = blk % Hh;
    int tid = threadIdx.x, warp = tid >> 5, lane = tid & 31;
    __shared__ float ps[Dd];
    __shared__ float outs[24];
    __shared__ float gls[MMm];
    for (int q = tid; q < Dd; q += 256) ps[q] = pooled[b*Dd + q];
    __syncthreads();
    for (int o = warp; o < 24; o += 8) {
        const float* wcol; int stride; float bias;
        if (o < 16) { wcol = gate_w + h*MMm + o;      stride = Hh*MMm; bias = gate_b[h*MMm + o]; }
        else        { int r = o-16; wcol = mod_w + h*RMm + r; stride = Hh*RMm; bias = mod_b[h*RMm + r]; }
        float s = 0.f;
        for (int dI = lane; dI < Dd; dI += 32) s += ps[dI] * wcol[(size_t)dI * stride];
        #pragma unroll
        for (int off = 16; off; off >>= 1) s += __shfl_xor_sync(0xffffffffu, s, off);
        if (lane == 0) outs[o] = s + bias;
    }
    __syncthreads();
    if (tid < MMm) {
        float gl = outs[tid];
        #pragma unroll
        for (int r = 0; r < RMm; r++) gl += outs[16 + r] * mod_basis[(r*Hh + h)*MMm + tid];
        gls[tid] = gl;
    }
    __syncthreads();
    if (tid == 0) {
        float mx = -1e30f;
        for (int m = 0; m < MMm; m++) mx = fmaxf(mx, gls[m]);
        float e[MMm], sm = 0.f;
        for (int m = 0; m < MMm; m++) { e[m] = expf(gls[m] - mx); sm += e[m]; }
        float inv = 1.f / sm;
        for (int m = 0; m < MMm; m++) wts[(b*Hh + h)*MMm + m] = e[m] * inv;
    }
}

// ---------------- wave mask -> causal Toeplitz kernel row (only d>=0 needed) ----------------
// straight-through heaviside is identity in forward => density = sigmoid(STEP_A * kern)
__global__ void __launch_bounds__(256) wave_k(const float* __restrict__ wts,
    const float* __restrict__ freqs, const float* __restrict__ amps,
    const float* __restrict__ phases, float* __restrict__ ckr)
{
    int b = blockIdx.z, h = blockIdx.y;
    int d = blockIdx.x * 256 + threadIdx.x;
    __shared__ float fs[MMm*WWw*2], as_[MMm*WWw], ph_[MMm*WWw], ws[MMm];
    int t = threadIdx.x;
    fs[t] = freqs[h*MMm*WWw*2 + t];                       // 256 values exactly
    if (t < MMm*WWw) { as_[t] = amps[h*MMm*WWw + t]; ph_[t] = phases[h*MMm*WWw + t]; }
    if (t < MMm) ws[t] = wts[(b*Hh + h)*MMm + t];
    __syncthreads();
    float p1 = d * (1.f/Ss);
    float p2 = (d == 0) ? 0.f : sqrtf((float)d + 1e-6f) * 0.03125f;   // /sqrt(1024)
    float kern = 0.f;
    #pragma unroll
    for (int m = 0; m < MMm; m++) {
        float acc = 0.f;
        #pragma unroll
        for (int w = 0; w < WWw; w++) {
            int iw = m*WWw + w;
            acc += as_[iw] * sinf(fs[iw*2+0]*p1 + fs[iw*2+1]*p2 + ph_[iw]);
        }
        kern += ws[m] * acc;
    }
    float dens = 1.f / (1.f + expf(-6.f * kern));                       // STEP_A = 6
    float win  = expf(-(float)d * (float)d * (1.f/131072.f));           // 2*(S/4)^2
    ckr[(b*Hh + h)*Ss + d] = 3.f * dens * win;                          // ALPHA = 3
}

// ---------------- flash attention: Toeplitz + qm/km + rank-8 content, causal ----------------
__global__ void __launch_bounds__(256) attn_k(const float* __restrict__ qc,
    const float* __restrict__ kc, const float* __restrict__ qm,
    const float* __restrict__ km, const float* __restrict__ ckr,
    const float* __restrict__ v,  float* __restrict__ ctx)
{
    const int b = blockIdx.z, h = blockIdx.y;
    const int iBase = blockIdx.x * 8;
    const int tid = threadIdx.x, warp = tid >> 5, lane = tid & 31;
    const int i = iBase + warp;
    const float cmix = 0.0530330085889911f;   // MIX / sqrt(CR)

    __shared__ float ck_s[Ss];
    __shared__ float kc_s[64][CRc];
    __shared__ float km_s[64];
    __shared__ float p_s[8][64];

    for (int o = tid; o < Ss; o += 256) ck_s[o] = ckr[(b*Hh + h)*Ss + o];

    float qcr[CRc];
    #pragma unroll
    for (int c = 0; c < CRc; c++) qcr[c] = qc[((size_t)(b*Ss + i)*Hh + h)*CRc + c];
    const float qmi = qm[(b*Ss + i)*Hh + h];

    float mrun = -1e30f, lrun = 0.f;
    float acc0 = 0.f, acc1 = 0.f;
    const int d0 = lane * 2;
    const int jEnd = iBase + 8;

    for (int jb = 0; jb < jEnd; jb += 64) {
        __syncthreads();
        {
            int idx = tid;
            #pragma unroll
            for (int g = 0; g < 2; g++, idx += 256) {
                int jj = idx >> 3, c = idx & 7;
                kc_s[jj][c] = kc[((size_t)(b*Ss + jb + jj)*Hh + h)*CRc + c];
            }
            if (tid < 64) km_s[tid] = km[(b*Ss + jb + tid)*Hh + h];
        }
        __syncthreads();

        float s1 = -1e30f, s2 = -1e30f;
        {
            int j1 = jb + lane;
            if (j1 <= i) {
                float dot = 0.f;
                #pragma unroll
                for (int c = 0; c < CRc; c++) dot += qcr[c] * kc_s[lane][c];
                s1 = ck_s[i - j1] + qmi + km_s[lane] + cmix * dot;
            }
            int j2 = jb + lane + 32;
            if (j2 <= i) {
                float dot = 0.f;
                #pragma unroll
                for (int c = 0; c < CRc; c++) dot += qcr[c] * kc_s[lane + 32][c];
                s2 = ck_s[i - j2] + qmi + km_s[lane + 32] + cmix * dot;
            }
        }
        float cmax = fmaxf(s1, s2);
        #pragma unroll
        for (int o = 16; o; o >>= 1) cmax = fmaxf(cmax, __shfl_xor_sync(0xffffffffu, cmax, o));
        float mnew  = fmaxf(mrun, cmax);
        float scale = __expf(mrun - mnew);
        float p1 = __expf(s1 - mnew);
        float p2 = __expf(s2 - mnew);
        float ps = p1 + p2;
        #pragma unroll
        for (int o = 16; o; o >>= 1) ps += __shfl_xor_sync(0xffffffffu, ps, o);
        lrun = lrun * scale + ps;
        acc0 *= scale; acc1 *= scale;
        p_s[warp][lane] = p1; p_s[warp][lane + 32] = p2;
        __syncwarp();
        const float2* vrow = (const float2*)(v + (size_t)(b*Ss + jb)*Dd + h*HDd + d0);
        #pragma unroll 8
        for (int jj = 0; jj < 64; jj++) {
            float2 vv = vrow[(size_t)jj * (Dd/2)];
            float p = p_s[warp][jj];
            acc0 += p * vv.x; acc1 += p * vv.y;
        }
        __syncwarp();
        mrun = mnew;
    }
    float inv = 1.f / lrun;
    float2* orow = (float2*)(ctx + (size_t)(b*Ss + i)*Dd + h*HDd + d0);
    *orow = make_float2(acc0 * inv, acc1 * inv);
}

// ---------------- fused residual + LayerNorm ----------------
__global__ void __launch_bounds__(256) ln_k(const float* __restrict__ a,
    const float* __restrict__ r, const float* __restrict__ g,
    const float* __restrict__ bta, float* __restrict__ out)
{
    int row = blockIdx.x;
    size_t base = (size_t)row * Dd;
    int tid = threadIdx.x;
    float vals[4], s = 0.f, s2 = 0.f;
    #pragma unroll
    for (int q = 0; q < 4; q++) {
        int idx = tid + q*256;
        float xv = a[base + idx] + r[base + idx];
        vals[q] = xv; s += xv; s2 += xv*xv;
    }
    __shared__ float red[64];
    #pragma unroll
    for (int o = 16; o; o >>= 1) {
        s  += __shfl_xor_sync(0xffffffffu, s,  o);
        s2 += __shfl_xor_sync(0xffffffffu, s2, o);
    }
    int warp = tid >> 5, lane = tid & 31;
    if (lane == 0) { red[warp] = s; red[32 + warp] = s2; }
    __syncthreads();
    if (warp == 0) {
        float a1 = (lane < 8) ? red[lane] : 0.f;
        float a2 = (lane < 8) ? red[32 + lane] : 0.f;
        #pragma unroll
        for (int o = 4; o; o >>= 1) {
            a1 += __shfl_xor_sync(0xffffffffu, a1, o);
            a2 += __shfl_xor_sync(0xffffffffu, a2, o);
        }
        if (lane == 0) { red[0] = a1; red[1] = a2; }
    }
    __syncthreads();
    float mean = red[0] * (1.f/Dd);
    float var  = red[1] * (1.f/Dd) - mean*mean;
    float rstd = rsqrtf(var + 1e-5f);
    #pragma unroll
    for (int q = 0; q < 4; q++) {
        int idx = tid + q*256;
        out[base + idx] = (vals[q] - mean) * rstd * g[idx] + bta[idx];
    }
}

// ---------------- launch ----------------
extern "C" void kernel_launch(void* const* d_in, const int* in_sizes, int n_in,
                              void* d_out, int out_size)
{
    const float* x      = (const float*)d_in[0];
    const float* v_w    = (const float*)d_in[1];
    const float* v_b    = (const float*)d_in[2];
    const float* out_w  = (const float*)d_in[3];
    const float* out_b  = (const float*)d_in[4];
    const float* qmod_w = (const float*)d_in[5];
    const float* qmod_b = (const float*)d_in[6];
    const float* kmod_w = (const float*)d_in[7];
    const float* kmod_b = (const float*)d_in[8];
    const float* gate_w = (const float*)d_in[9];
    const float* gate_b = (const float*)d_in[10];
    const float* mod_w  = (const float*)d_in[11];
    const float* mod_b  = (const float*)d_in[12];
    const float* mod_basis = (const float*)d_in[13];
    const float* freqs  = (const float*)d_in[14];
    const float* amps   = (const float*)d_in[15];
    const float* phases = (const float*)d_in[16];
    const float* cq_w   = (const float*)d_in[17];
    const float* ck_w   = (const float*)d_in[18];
    const float* ffn_w1 = (const float*)d_in[19];
    const float* ffn_b1 = (const float*)d_in[20];
    const float* ffn_w2 = (const float*)d_in[21];
    const float* ffn_b2 = (const float*)d_in[22];
    const float* ln1_g  = (const float*)d_in[23];
    const float* ln1_b  = (const float*)d_in[24];
    const float* ln2_g  = (const float*)d_in[25];
    const float* ln2_b  = (const float*)d_in[26];
    float* out = (float*)d_out;

    float *pv, *ppp, *ppool, *pwts, *pck, *pqm, *pkm, *pqc, *pkc, *pctx, *pao, *ph, *pffn, *pf2;
    cudaGetSymbolAddress((void**)&pv,   g_v);
    cudaGetSymbolAddress((void**)&ppp,  g_pp);
    cudaGetSymbolAddress((void**)&ppool,g_pool);
    cudaGetSymbolAddress((void**)&pwts, g_wts);
    cudaGetSymbolAddress((void**)&pck,  g_ckr);
    cudaGetSymbolAddress((void**)&pqm,  g_qm);
    cudaGetSymbolAddress((void**)&pkm,  g_km);
    cudaGetSymbolAddress((void**)&pqc,  g_qc);
    cudaGetSymbolAddress((void**)&pkc,  g_kc);
    cudaGetSymbolAddress((void**)&pctx, g_ctx);
    cudaGetSymbolAddress((void**)&pao,  g_ao);
    cudaGetSymbolAddress((void**)&ph,   g_h);
    cudaGetSymbolAddress((void**)&pffn, g_ffn);
    cudaGetSymbolAddress((void**)&pf2,  g_f2);

    // projections from x
    gemm_k<false><<<dim3(16,16), 256>>>(x, v_w,    v_b,     pv,  ROWS, 1024, 1024);
    gemm_k<false><<<dim3(1, 16), 256>>>(x, qmod_w, qmod_b,  pqm, ROWS, 16,   1024);
    gemm_k<false><<<dim3(1, 16), 256>>>(x, kmod_w, kmod_b,  pkm, ROWS, 16,   1024);
    gemm_k<false><<<dim3(2, 16), 256>>>(x, cq_w,   nullptr, pqc, ROWS, 128,  1024);
    gemm_k<false><<<dim3(2, 16), 256>>>(x, ck_w,   nullptr, pkc, ROWS, 128,  1024);

    // gating path
    pool1_k<<<dim3(8,4), 256>>>(x, ppp);
    pool2_k<<<8, 256>>>(ppp, ppool);
    gating_k<<<Bb*Hh, 256>>>(ppool, gate_w, gate_b, mod_w, mod_b, mod_basis, pwts);
    wave_k<<<dim3(Ss/256, Hh, Bb), 256>>>(pwts, freqs, amps, phases, pck);

    // attention
    attn_k<<<dim3(Ss/8, Hh, Bb), 256>>>(pqc, pkc, pqm, pkm, pck, pv, pctx);
    gemm_k<false><<<dim3(16,16), 256>>>(pctx, out_w, out_b, pao, ROWS, 1024, 1024);

    // LN1 + FFN + LN2
    ln_k<<<ROWS, 256>>>(x, pao, ln1_g, ln1_b, ph);
    gemm_k<true ><<<dim3(64,16), 256>>>(ph,   ffn_w1, ffn_b1, pffn, ROWS, FFD,  1024);
    gemm_k<false><<<dim3(16,16), 256>>>(pffn, ffn_w2, ffn_b2, pf2,  ROWS, 1024, FFD);
    ln_k<<<ROWS, 256>>>(ph, pf2, ln2_g, ln2_b, out);
}

// round 2
// speedup vs baseline: 2.0064x; 2.0064x over previous
#include <cuda_runtime.h>
#include <math.h>
#include <stdint.h>

// ---------------- problem constants ----------------
#define Bb   2
#define Ss   1024
#define Dd   1024
#define Hh   16
#define HDd  64
#define MMm  16
#define WWw  8
#define RMm  8
#define CRc  8
#define FFD  4096
#define ROWS (Bb*Ss)          // 2048
#define NPK  384              // packed projection width (16 qm + 16 km + 128 qc + 128 kc + 96 pad)

// ---------------- scratch (no allocations allowed) ----------------
__device__ float g_v    [Bb*Ss*Dd];
__device__ float g_pp   [4*Bb*Dd];
__device__ float g_pool [Bb*Dd];
__device__ float g_wts  [Bb*Hh*MMm];
__device__ float g_ckr  [Bb*Hh*Ss];
__device__ float g_wpack[Dd*NPK];
__device__ float g_bpack[NPK];
__device__ float g_proj [ROWS*NPK];
__device__ float g_ctx  [Bb*Ss*Dd];
__device__ float g_ao   [Bb*Ss*Dd];
__device__ float g_h    [Bb*Ss*Dd];
__device__ float g_ffn  [Bb*Ss*FFD];
__device__ float g_f2   [Bb*Ss*Dd];

// ---------------- tf32 helpers ----------------
__device__ __forceinline__ float cvt_tf32(float x) {
    uint32_t u;
    asm("cvt.rna.tf32.f32 %0, %1;" : "=r"(u) : "f"(x));
    return __uint_as_float(u);
}

__device__ __forceinline__ void mma_tf32(float* c, const uint32_t* a, const uint32_t* b) {
    asm volatile(
        "mma.sync.aligned.m16n8k8.row.col.f32.tf32.tf32.f32 "
        "{%0,%1,%2,%3}, {%4,%5,%6,%7}, {%8,%9}, {%0,%1,%2,%3};"
        : "+f"(c[0]), "+f"(c[1]), "+f"(c[2]), "+f"(c[3])
        : "r"(a[0]), "r"(a[1]), "r"(a[2]), "r"(a[3]), "r"(b[0]), "r"(b[1]));
}

// ---------------- tensor-core tf32 GEMM: C = A[M,K] @ B[K,N] + bias, opt GELU ----
// Requirements (all satisfied by our launches): M%128==0, N%128==0, K%16==0.
#define TBM 128
#define TBN 128
#define TBK 16
#define TAP 20      // A smem row stride (floats): conflict-free + 16B-aligned (80B)
#define TBP 136     // B smem row stride (floats): conflict-free + 16B-aligned (544B)

template<bool GELU>
__global__ void __launch_bounds__(256) gemm_tc(const float* __restrict__ A,
                                               const float* __restrict__ Bm,
                                               const float* __restrict__ bias,
                                               float* __restrict__ C,
                                               int M, int N, int K)
{
    __shared__ float As[2][TBM][TAP];
    __shared__ float Bs[2][TBK][TBP];

    const int tid  = threadIdx.x;
    const int lane = tid & 31;
    const int warp = tid >> 5;
    const int wm   = warp & 1;           // 2 warps in M
    const int wn   = warp >> 1;          // 4 warps in N
    const int m0   = blockIdx.y * TBM;
    const int n0   = blockIdx.x * TBN;

    // staging indices
    const int ar  = tid >> 1;            // 0..127
    const int ac  = (tid & 1) * 8;       // 0 or 8
    const int br  = tid >> 4;            // 0..15
    const int bc  = (tid & 15) * 8;      // 0..120

    const float* Abase = A + (size_t)(m0 + ar) * K + ac;
    const float* Bbase = Bm + (size_t)br * N + n0 + bc;

    float4 ra0, ra1, rb0, rb1;

    // preload tile 0
    ra0 = *(const float4*)(Abase);
    ra1 = *(const float4*)(Abase + 4);
    rb0 = *(const float4*)(Bbase);
    rb1 = *(const float4*)(Bbase + 4);

    float acc[4][4][4];
    #pragma unroll
    for (int mt = 0; mt < 4; mt++)
        #pragma unroll
        for (int nt = 0; nt < 4; nt++)
            #pragma unroll
            for (int q = 0; q < 4; q++) acc[mt][nt][q] = 0.f;

    // store tile 0 (with tf32 rounding)
    {
        float* ap = &As[0][ar][ac];
        ap[0]=cvt_tf32(ra0.x); ap[1]=cvt_tf32(ra0.y); ap[2]=cvt_tf32(ra0.z); ap[3]=cvt_tf32(ra0.w);
        ap[4]=cvt_tf32(ra1.x); ap[5]=cvt_tf32(ra1.y); ap[6]=cvt_tf32(ra1.z); ap[7]=cvt_tf32(ra1.w);
        float* bp = &Bs[0][br][bc];
        bp[0]=cvt_tf32(rb0.x); bp[1]=cvt_tf32(rb0.y); bp[2]=cvt_tf32(rb0.z); bp[3]=cvt_tf32(rb0.w);
        bp[4]=cvt_tf32(rb1.x); bp[5]=cvt_tf32(rb1.y); bp[6]=cvt_tf32(rb1.z); bp[7]=cvt_tf32(rb1.w);
    }
    __syncthreads();

    const int T = K / TBK;
    for (int t = 0; t < T; t++) {
        const int buf = t & 1;
        if (t + 1 < T) {
            const float* Ap = Abase + (t + 1) * TBK;
            ra0 = *(const float4*)(Ap);
            ra1 = *(const float4*)(Ap + 4);
            const float* Bp = Bbase + (size_t)(t + 1) * TBK * N;
            rb0 = *(const float4*)(Bp);
            rb1 = *(const float4*)(Bp + 4);
        }

        #pragma unroll
        for (int kk = 0; kk < TBK; kk += 8) {
            uint32_t af[4][4];
            #pragma unroll
            for (int mt = 0; mt < 4; mt++) {
                int r = wm*64 + mt*16 + (lane >> 2);
                int c = kk + (lane & 3);
                af[mt][0] = __float_as_uint(As[buf][r    ][c    ]);
                af[mt][1] = __float_as_uint(As[buf][r + 8][c    ]);
                af[mt][2] = __float_as_uint(As[buf][r    ][c + 4]);
                af[mt][3] = __float_as_uint(As[buf][r + 8][c + 4]);
            }
            uint32_t bf[4][2];
            #pragma unroll
            for (int nt = 0; nt < 4; nt++) {
                int n = wn*32 + nt*8 + (lane >> 2);
                bf[nt][0] = __float_as_uint(Bs[buf][kk     + (lane & 3)][n]);
                bf[nt][1] = __float_as_uint(Bs[buf][kk + 4 + (lane & 3)][n]);
            }
            #pragma unroll
            for (int mt = 0; mt < 4; mt++)
                #pragma unroll
                for (int nt = 0; nt < 4; nt++)
                    mma_tf32(acc[mt][nt], af[mt], bf[nt]);
        }

        if (t + 1 < T) {
            const int nb = (t + 1) & 1;
            float* ap = &As[nb][ar][ac];
            ap[0]=cvt_tf32(ra0.x); ap[1]=cvt_tf32(ra0.y); ap[2]=cvt_tf32(ra0.z); ap[3]=cvt_tf32(ra0.w);
            ap[4]=cvt_tf32(ra1.x); ap[5]=cvt_tf32(ra1.y); ap[6]=cvt_tf32(ra1.z); ap[7]=cvt_tf32(ra1.w);
            float* bp = &Bs[nb][br][bc];
            bp[0]=cvt_tf32(rb0.x); bp[1]=cvt_tf32(rb0.y); bp[2]=cvt_tf32(rb0.z); bp[3]=cvt_tf32(rb0.w);
            bp[4]=cvt_tf32(rb1.x); bp[5]=cvt_tf32(rb1.y); bp[6]=cvt_tf32(rb1.z); bp[7]=cvt_tf32(rb1.w);
        }
        __syncthreads();
    }

    // epilogue
    #pragma unroll
    for (int mt = 0; mt < 4; mt++) {
        #pragma unroll
        for (int nt = 0; nt < 4; nt++) {
            int r  = m0 + wm*64 + mt*16 + (lane >> 2);
            int cc = n0 + wn*32 + nt*8 + 2*(lane & 3);
            float b0 = bias ? bias[cc]     : 0.f;
            float b1 = bias ? bias[cc + 1] : 0.f;
            float v0 = acc[mt][nt][0] + b0;
            float v1 = acc[mt][nt][1] + b1;
            float v2 = acc[mt][nt][2] + b0;
            float v3 = acc[mt][nt][3] + b1;
            if (GELU) {
                v0 = 0.5f * v0 * (1.f + erff(v0 * 0.70710678118654752f));
                v1 = 0.5f * v1 * (1.f + erff(v1 * 0.70710678118654752f));
                v2 = 0.5f * v2 * (1.f + erff(v2 * 0.70710678118654752f));
                v3 = 0.5f * v3 * (1.f + erff(v3 * 0.70710678118654752f));
            }
            *(float2*)(C + (size_t)r * N + cc)       = make_float2(v0, v1);
            *(float2*)(C + (size_t)(r + 8) * N + cc) = make_float2(v2, v3);
        }
    }
}

// ---------------- pack qmod/kmod/cq/ck weights into [D, NPK] ----------------
__global__ void pack_k(const float* __restrict__ qmod_w, const float* __restrict__ qmod_b,
                       const float* __restrict__ kmod_w, const float* __restrict__ kmod_b,
                       const float* __restrict__ cq_w,   const float* __restrict__ ck_w,
                       float* __restrict__ wpack, float* __restrict__ bpack)
{
    int idx = blockIdx.x * 256 + threadIdx.x;          // over D*NPK
    int k = idx / NPK, c = idx % NPK;
    float v = 0.f;
    if      (c < 16)  v = qmod_w[k*Hh + c];
    else if (c < 32)  v = kmod_w[k*Hh + (c - 16)];
    else if (c < 160) v = cq_w[k*(Hh*CRc) + (c - 32)];
    else if (c < 288) v = ck_w[k*(Hh*CRc) + (c - 160)];
    wpack[idx] = v;
    if (k == 0) {
        float bv = 0.f;
        if (c < 16)      bv = qmod_b[c];
        else if (c < 32) bv = kmod_b[c - 16];
        bpack[c] = bv;
    }
}

// ---------------- pooled mean over S (two stage, deterministic) ----------------
__global__ void pool1_k(const float* __restrict__ x, float* __restrict__ pp)
{
    int idx = blockIdx.x * 256 + threadIdx.x;       // 0..2047 over (b,d)
    int sl  = blockIdx.y;                           // 0..3
    int b = idx >> 10, d = idx & 1023;
    const float* xp = x + (size_t)(b*Ss + sl*256)*Dd + d;
    float s0=0,s1=0,s2=0,s3=0;
    for (int q = 0; q < 256; q += 4) {
        s0 += xp[(size_t)(q+0)*Dd];
        s1 += xp[(size_t)(q+1)*Dd];
        s2 += xp[(size_t)(q+2)*Dd];
        s3 += xp[(size_t)(q+3)*Dd];
    }
    pp[sl*2048 + idx] = (s0+s1)+(s2+s3);
}

__global__ void pool2_k(const float* __restrict__ pp, float* __restrict__ pooled)
{
    int idx = blockIdx.x * 256 + threadIdx.x;
    pooled[idx] = (pp[idx] + pp[2048+idx] + pp[4096+idx] + pp[6144+idx]) * (1.f/Ss);
}

// ---------------- gating (straight-through top-k == softmax in fwd) ----------------
__global__ void __launch_bounds__(256) gating_k(const float* __restrict__ pooled,
    const float* __restrict__ gate_w, const float* __restrict__ gate_b,
    const float* __restrict__ mod_w,  const float* __restrict__ mod_b,
    const float* __restrict__ mod_basis, float* __restrict__ wts)
{
    int blk = blockIdx.x;
    int b = blk / Hh, h = blk % Hh;
    int tid = threadIdx.x, warp = tid >> 5, lane = tid & 31;
    __shared__ float ps[Dd];
    __shared__ float outs[24];
    __shared__ float gls[MMm];
    for (int q = tid; q < Dd; q += 256) ps[q] = pooled[b*Dd + q];
    __syncthreads();
    for (int o = warp; o < 24; o += 8) {
        const float* wcol; int stride; float bias;
        if (o < 16) { wcol = gate_w + h*MMm + o;      stride = Hh*MMm; bias = gate_b[h*MMm + o]; }
        else        { int r = o-16; wcol = mod_w + h*RMm + r; stride = Hh*RMm; bias = mod_b[h*RMm + r]; }
        float s = 0.f;
        for (int dI = lane; dI < Dd; dI += 32) s += ps[dI] * wcol[(size_t)dI * stride];
        #pragma unroll
        for (int off = 16; off; off >>= 1) s += __shfl_xor_sync(0xffffffffu, s, off);
        if (lane == 0) outs[o] = s + bias;
    }
    __syncthreads();
    if (tid < MMm) {
        float gl = outs[tid];
        #pragma unroll
        for (int r = 0; r < RMm; r++) gl += outs[16 + r] * mod_basis[(r*Hh + h)*MMm + tid];
        gls[tid] = gl;
    }
    __syncthreads();
    if (tid == 0) {
        float mx = -1e30f;
        for (int m = 0; m < MMm; m++) mx = fmaxf(mx, gls[m]);
        float e[MMm], sm = 0.f;
        for (int m = 0; m < MMm; m++) { e[m] = expf(gls[m] - mx); sm += e[m]; }
        float inv = 1.f / sm;
        for (int m = 0; m < MMm; m++) wts[(b*Hh + h)*MMm + m] = e[m] * inv;
    }
}

// ---------------- wave mask -> causal Toeplitz kernel row ----------------
__global__ void __launch_bounds__(256) wave_k(const float* __restrict__ wts,
    const float* __restrict__ freqs, const float* __restrict__ amps,
    const float* __restrict__ phases, float* __restrict__ ckr)
{
    int b = blockIdx.z, h = blockIdx.y;
    int d = blockIdx.x * 256 + threadIdx.x;
    __shared__ float fs[MMm*WWw*2], as_[MMm*WWw], ph_[MMm*WWw], ws[MMm];
    int t = threadIdx.x;
    fs[t] = freqs[h*MMm*WWw*2 + t];
    if (t < MMm*WWw) { as_[t] = amps[h*MMm*WWw + t]; ph_[t] = phases[h*MMm*WWw + t]; }
    if (t < MMm) ws[t] = wts[(b*Hh + h)*MMm + t];
    __syncthreads();
    float p1 = d * (1.f/Ss);
    float p2 = (d == 0) ? 0.f : sqrtf((float)d + 1e-6f) * 0.03125f;
    float kern = 0.f;
    #pragma unroll
    for (int m = 0; m < MMm; m++) {
        float acc = 0.f;
        #pragma unroll
        for (int w = 0; w < WWw; w++) {
            int iw = m*WWw + w;
            acc += as_[iw] * sinf(fs[iw*2+0]*p1 + fs[iw*2+1]*p2 + ph_[iw]);
        }
        kern += ws[m] * acc;
    }
    float dens = 1.f / (1.f + expf(-6.f * kern));
    float win  = expf(-(float)d * (float)d * (1.f/131072.f));
    ckr[(b*Hh + h)*Ss + d] = 3.f * dens * win;
}

// ---------------- flash attention (Toeplitz + qm/km + rank-8 content) ----------------
__global__ void __launch_bounds__(256) attn_k(const float* __restrict__ proj,
    const float* __restrict__ ckr, const float* __restrict__ v,
    float* __restrict__ ctx)
{
    const int b = blockIdx.z, h = blockIdx.y;
    const int iBase = blockIdx.x * 8;
    const int tid = threadIdx.x, warp = tid >> 5, lane = tid & 31;
    const int i = iBase + warp;
    const float cmix = 0.0530330085889911f;   // MIX / sqrt(CR)

    __shared__ float ck_s[Ss];
    __shared__ float kc_s[64][CRc];
    __shared__ float km_s[64];
    __shared__ float p_s[8][64];

    for (int o = tid; o < Ss; o += 256) ck_s[o] = ckr[(b*Hh + h)*Ss + o];

    float qcr[CRc];
    #pragma unroll
    for (int c = 0; c < CRc; c++)
        qcr[c] = proj[(size_t)(b*Ss + i)*NPK + 32 + h*CRc + c];
    const float qmi = proj[(size_t)(b*Ss + i)*NPK + h];

    float mrun = -1e30f, lrun = 0.f;
    float acc0 = 0.f, acc1 = 0.f;
    const int d0 = lane * 2;
    const int jEnd = iBase + 8;

    for (int jb = 0; jb < jEnd; jb += 64) {
        __syncthreads();
        {
            int idx = tid;
            #pragma unroll
            for (int g = 0; g < 2; g++, idx += 256) {
                int jj = idx >> 3, c = idx & 7;
                kc_s[jj][c] = proj[(size_t)(b*Ss + jb + jj)*NPK + 160 + h*CRc + c];
            }
            if (tid < 64) km_s[tid] = proj[(size_t)(b*Ss + jb + tid)*NPK + 16 + h];
        }
        __syncthreads();

        float s1 = -1e30f, s2 = -1e30f;
        {
            int j1 = jb + lane;
            if (j1 <= i) {
                float dot = 0.f;
                #pragma unroll
                for (int c = 0; c < CRc; c++) dot += qcr[c] * kc_s[lane][c];
                s1 = ck_s[i - j1] + qmi + km_s[lane] + cmix * dot;
            }
            int j2 = jb + lane + 32;
            if (j2 <= i) {
                float dot = 0.f;
                #pragma unroll
                for (int c = 0; c < CRc; c++) dot += qcr[c] * kc_s[lane + 32][c];
                s2 = ck_s[i - j2] + qmi + km_s[lane + 32] + cmix * dot;
            }
        }
        float cmax = fmaxf(s1, s2);
        #pragma unroll
        for (int o = 16; o; o >>= 1) cmax = fmaxf(cmax, __shfl_xor_sync(0xffffffffu, cmax, o));
        float mnew  = fmaxf(mrun, cmax);
        float scale = __expf(mrun - mnew);
        float p1 = __expf(s1 - mnew);
        float p2 = __expf(s2 - mnew);
        float ps = p1 + p2;
        #pragma unroll
        for (int o = 16; o; o >>= 1) ps += __shfl_xor_sync(0xffffffffu, ps, o);
        lrun = lrun * scale + ps;
        acc0 *= scale; acc1 *= scale;
        p_s[warp][lane] = p1; p_s[warp][lane + 32] = p2;
        __syncwarp();
        const float2* vrow = (const float2*)(v + (size_t)(b*Ss + jb)*Dd + h*HDd + d0);
        #pragma unroll 8
        for (int jj = 0; jj < 64; jj++) {
            float2 vv = vrow[(size_t)jj * (Dd/2)];
            float p = p_s[warp][jj];
            acc0 += p * vv.x; acc1 += p * vv.y;
        }
        __syncwarp();
        mrun = mnew;
    }
    float inv = 1.f / lrun;
    float2* orow = (float2*)(ctx + (size_t)(b*Ss + i)*Dd + h*HDd + d0);
    *orow = make_float2(acc0 * inv, acc1 * inv);
}

// ---------------- fused residual + LayerNorm ----------------
__global__ void __launch_bounds__(256) ln_k(const float* __restrict__ a,
    const float* __restrict__ r, const float* __restrict__ g,
    const float* __restrict__ bta, float* __restrict__ out)
{
    int row = blockIdx.x;
    size_t base = (size_t)row * Dd;
    int tid = threadIdx.x;
    float vals[4], s = 0.f, s2 = 0.f;
    #pragma unroll
    for (int q = 0; q < 4; q++) {
        int idx = tid + q*256;
        float xv = a[base + idx] + r[base + idx];
        vals[q] = xv; s += xv; s2 += xv*xv;
    }
    __shared__ float red[64];
    #pragma unroll
    for (int o = 16; o; o >>= 1) {
        s  += __shfl_xor_sync(0xffffffffu, s,  o);
        s2 += __shfl_xor_sync(0xffffffffu, s2, o);
    }
    int warp = tid >> 5, lane = tid & 31;
    if (lane == 0) { red[warp] = s; red[32 + warp] = s2; }
    __syncthreads();
    if (warp == 0) {
        float a1 = (lane < 8) ? red[lane] : 0.f;
        float a2 = (lane < 8) ? red[32 + lane] : 0.f;
        #pragma unroll
        for (int o = 4; o; o >>= 1) {
            a1 += __shfl_xor_sync(0xffffffffu, a1, o);
            a2 += __shfl_xor_sync(0xffffffffu, a2, o);
        }
        if (lane == 0) { red[0] = a1; red[1] = a2; }
    }
    __syncthreads();
    float mean = red[0] * (1.f/Dd);
    float var  = red[1] * (1.f/Dd) - mean*mean;
    float rstd = rsqrtf(var + 1e-5f);
    #pragma unroll
    for (int q = 0; q < 4; q++) {
        int idx = tid + q*256;
        out[base + idx] = (vals[q] - mean) * rstd * g[idx] + bta[idx];
    }
}

// ---------------- launch ----------------
extern "C" void kernel_launch(void* const* d_in, const int* in_sizes, int n_in,
                              void* d_out, int out_size)
{
    const float* x      = (const float*)d_in[0];
    const float* v_w    = (const float*)d_in[1];
    const float* v_b    = (const float*)d_in[2];
    const float* out_w  = (const float*)d_in[3];
    const float* out_b  = (const float*)d_in[4];
    const float* qmod_w = (const float*)d_in[5];
    const float* qmod_b = (const float*)d_in[6];
    const float* kmod_w = (const float*)d_in[7];
    const float* kmod_b = (const float*)d_in[8];
    const float* gate_w = (const float*)d_in[9];
    const float* gate_b = (const float*)d_in[10];
    const float* mod_w  = (const float*)d_in[11];
    const float* mod_b  = (const float*)d_in[12];
    const float* mod_basis = (const float*)d_in[13];
    const float* freqs  = (const float*)d_in[14];
    const float* amps   = (const float*)d_in[15];
    const float* phases = (const float*)d_in[16];
    const float* cq_w   = (const float*)d_in[17];
    const float* ck_w   = (const float*)d_in[18];
    const float* ffn_w1 = (const float*)d_in[19];
    const float* ffn_b1 = (const float*)d_in[20];
    const float* ffn_w2 = (const float*)d_in[21];
    const float* ffn_b2 = (const float*)d_in[22];
    const float* ln1_g  = (const float*)d_in[23];
    const float* ln1_b  = (const float*)d_in[24];
    const float* ln2_g  = (const float*)d_in[25];
    const float* ln2_b  = (const float*)d_in[26];
    float* out = (float*)d_out;

    float *pv, *ppp, *ppool, *pwts, *pck, *pwp, *pbp, *pproj, *pctx, *pao, *ph, *pffn, *pf2;
    cudaGetSymbolAddress((void**)&pv,   g_v);
    cudaGetSymbolAddress((void**)&ppp,  g_pp);
    cudaGetSymbolAddress((void**)&ppool,g_pool);
    cudaGetSymbolAddress((void**)&pwts, g_wts);
    cudaGetSymbolAddress((void**)&pck,  g_ckr);
    cudaGetSymbolAddress((void**)&pwp,  g_wpack);
    cudaGetSymbolAddress((void**)&pbp,  g_bpack);
    cudaGetSymbolAddress((void**)&pproj,g_proj);
    cudaGetSymbolAddress((void**)&pctx, g_ctx);
    cudaGetSymbolAddress((void**)&pao,  g_ao);
    cudaGetSymbolAddress((void**)&ph,   g_h);
    cudaGetSymbolAddress((void**)&pffn, g_ffn);
    cudaGetSymbolAddress((void**)&pf2,  g_f2);

    // pack small projection weights, then 2 GEMMs from x
    pack_k<<<(Dd*NPK)/256, 256>>>(qmod_w, qmod_b, kmod_w, kmod_b, cq_w, ck_w, pwp, pbp);
    gemm_tc<false><<<dim3(8, 16), 256>>>(x, v_w, v_b, pv,    ROWS, 1024, 1024);
    gemm_tc<false><<<dim3(3, 16), 256>>>(x, pwp, pbp, pproj, ROWS, NPK,  1024);

    // gating path
    pool1_k<<<dim3(8,4), 256>>>(x, ppp);
    pool2_k<<<8, 256>>>(ppp, ppool);
    gating_k<<<Bb*Hh, 256>>>(ppool, gate_w, gate_b, mod_w, mod_b, mod_basis, pwts);
    wave_k<<<dim3(Ss/256, Hh, Bb), 256>>>(pwts, freqs, amps, phases, pck);

    // attention
    attn_k<<<dim3(Ss/8, Hh, Bb), 256>>>(pproj, pck, pv, pctx);
    gemm_tc<false><<<dim3(8, 16), 256>>>(pctx, out_w, out_b, pao, ROWS, 1024, 1024);

    // LN1 + FFN + LN2
    ln_k<<<ROWS, 256>>>(x, pao, ln1_g, ln1_b, ph);
    gemm_tc<true ><<<dim3(32, 16), 256>>>(ph,   ffn_w1, ffn_b1, pffn, ROWS, FFD,  1024);
    gemm_tc<false><<<dim3(8, 16), 256>>>(pffn,  ffn_w2, ffn_b2, pf2,  ROWS, 1024, FFD);
    ln_k<<<ROWS, 256>>>(ph, pf2, ln2_g, ln2_b, out);
}

// round 4
// speedup vs baseline: 2.1992x; 1.0961x over previous
#include <cuda_runtime.h>
#include <math.h>
#include <stdint.h>

// ---------------- problem constants ----------------
#define Bb   2
#define Ss   1024
#define Dd   1024
#define Hh   16
#define HDd  64
#define MMm  16
#define WWw  8
#define RMm  8
#define CRc  8
#define FFD  4096
#define ROWS (Bb*Ss)          // 2048
#define VPW  1408             // fused v(1024) + proj(384) width

// ---------------- scratch (no allocations allowed) ----------------
__device__ float g_xc  [ROWS*Dd];        // tf32-rounded x
__device__ float g_wcat[VPW*Dd];         // [N=1408][K=1024] transposed v_w + packed proj
__device__ float g_bcat[VPW];
__device__ float g_vp  [ROWS*VPW];       // v | qm | km | qc | kc
__device__ float g_owT [Dd*Dd];
__device__ float g_w1T [FFD*Dd];
__device__ float g_w2T [Dd*FFD];
__device__ float g_pp  [16*ROWS];
__device__ float g_pool[Bb*Dd];
__device__ float g_wts [Bb*Hh*MMm];
__device__ float g_ckr [Bb*Hh*Ss];
__device__ float g_ctx [ROWS*Dd];
__device__ float g_ao  [ROWS*Dd];
__device__ float g_h   [ROWS*Dd];
__device__ float g_hc  [ROWS*Dd];
__device__ float g_ffn [ROWS*FFD];
__device__ float g_f2  [ROWS*Dd];

// ---------------- helpers ----------------
__device__ __forceinline__ float cvt_tf32(float x) {
    uint32_t u;
    asm("cvt.rna.tf32.f32 %0, %1;" : "=r"(u) : "f"(x));
    return __uint_as_float(u);
}
__device__ __forceinline__ uint32_t smem_u32(const void* p) {
    uint32_t a;
    asm("{ .reg .u64 t; cvta.to.shared.u64 t, %1; cvt.u32.u64 %0, t; }" : "=r"(a) : "l"(p));
    return a;
}
__device__ __forceinline__ void mma_tf32(float* c, const uint32_t* a, const uint32_t* b) {
    asm volatile(
        "mma.sync.aligned.m16n8k8.row.col.f32.tf32.tf32.f32 "
        "{%0,%1,%2,%3}, {%4,%5,%6,%7}, {%8,%9}, {%0,%1,%2,%3};"
        : "+f"(c[0]), "+f"(c[1]), "+f"(c[2]), "+f"(c[3])
        : "r"(a[0]), "r"(a[1]), "r"(a[2]), "r"(a[3]), "r"(b[0]), "r"(b[1]));
}
__device__ __forceinline__ void cpa16(uint32_t dst, const void* src) {
    asm volatile("cp.async.cg.shared.global [%0], [%1], 16;" :: "r"(dst), "l"(src));
}
#define CPA_COMMIT() asm volatile("cp.async.commit_group;" ::: "memory")

// ---------------- mma.sync tf32 GEMM: C[M,N] = A[M,K] @ Bt[N,K]^T + bias -------
// M,N multiples of 128; K multiple of 16. A and Bt both K-major, tf32-prerounded.
// SMEM layout per stage: A 128 rows x 64B, then B 128 rows x 64B (16 KB / stage).
// Swizzle: 16B unit u of row r stored at unit (u ^ (r&3)).  Fragment loads use a
// logical k remap  (c, c+4) -> smem cols (2c, 2c+1)  so all LDS are 64-bit.
#define ST_BYTES 16384

template<bool GELU, bool CVT>
__global__ void __launch_bounds__(256, 2)
gemm5(const float* __restrict__ A, const float* __restrict__ Bt,
      const float* __restrict__ bias, float* __restrict__ C,
      int M, int N, int K)
{
    __shared__ float4 smem[3 * 1024];          // 3 stages * 16 KB = 48 KB
    const int tid = threadIdx.x, lane = tid & 31, warp = tid >> 5;
    const int wm = warp & 1, wn = warp >> 1;   // warp tile 64x32
    const int rr = lane >> 2, cl = lane & 3;
    const int m0 = blockIdx.y * 128, n0 = blockIdx.x * 128;
    const float* Arow = A  + (size_t)m0 * K;
    const float* Brow = Bt + (size_t)n0 * K;
    const uint32_t sbase = smem_u32(smem);
    const int T = K >> 4;

    float acc[4][4][4];
    #pragma unroll
    for (int mt = 0; mt < 4; mt++)
        #pragma unroll
        for (int nt = 0; nt < 4; nt++)
            #pragma unroll
            for (int q = 0; q < 4; q++) acc[mt][nt][q] = 0.f;

    auto stage = [&](int t) {
        const uint32_t sb = sbase + (t % 3) * ST_BYTES;
        const int k0 = t << 4;
        #pragma unroll
        for (int q = 0; q < 2; q++) {
            int ch = q * 256 + tid;            // 0..511
            int row = ch >> 2, u = ch & 3;
            uint32_t off = row * 64 + ((u ^ (row & 3)) << 4);
            cpa16(sb + off,        Arow + (size_t)row * K + k0 + u * 4);
            cpa16(sb + 8192 + off, Brow + (size_t)row * K + k0 + u * 4);
        }
        CPA_COMMIT();
    };

    stage(0); stage(1);
    for (int t = 0; t < T; t++) {
        if (t < T - 1) asm volatile("cp.async.wait_group 1;" ::: "memory");
        else           asm volatile("cp.async.wait_group 0;" ::: "memory");
        __syncthreads();
        const uint32_t sA = sbase + (t % 3) * ST_BYTES;
        const uint32_t sB = sA + 8192;

        #pragma unroll
        for (int kk = 0; kk < 2; kk++) {
            const int u = kk * 4 + cl;
            // same (row&3) for every row this thread touches -> one swizzle offset
            const uint32_t swzo = (((((u >> 1) ^ (rr & 3)) << 1) | (u & 1)) << 3);
            uint32_t af[4][4], bf[4][2];
            #pragma unroll
            for (int mt = 0; mt < 4; mt++) {
                const int r = wm * 64 + mt * 16 + rr;
                float lx, ly, hx, hy;
                asm("ld.shared.v2.f32 {%0,%1}, [%2];"
                    : "=f"(lx), "=f"(ly) : "r"(sA + r * 64 + swzo));
                asm("ld.shared.v2.f32 {%0,%1}, [%2];"
                    : "=f"(hx), "=f"(hy) : "r"(sA + (r + 8) * 64 + swzo));
                af[mt][0] = __float_as_uint(lx); af[mt][1] = __float_as_uint(hx);
                af[mt][2] = __float_as_uint(ly); af[mt][3] = __float_as_uint(hy);
            }
            #pragma unroll
            for (int nt = 0; nt < 4; nt++) {
                const int n = wn * 32 + nt * 8 + rr;
                float bx, by;
                asm("ld.shared.v2.f32 {%0,%1}, [%2];"
                    : "=f"(bx), "=f"(by) : "r"(sB + n * 64 + swzo));
                bf[nt][0] = __float_as_uint(bx); bf[nt][1] = __float_as_uint(by);
            }
            #pragma unroll
            for (int mt = 0; mt < 4; mt++)
                #pragma unroll
                for (int nt = 0; nt < 4; nt++)
                    mma_tf32(acc[mt][nt], af[mt], bf[nt]);
        }
        __syncthreads();
        if (t + 2 < T) stage(t + 2);
    }

    // epilogue
    #pragma unroll
    for (int mt = 0; mt < 4; mt++) {
        #pragma unroll
        for (int nt = 0; nt < 4; nt++) {
            int r  = m0 + wm * 64 + mt * 16 + rr;
            int cc = n0 + wn * 32 + nt * 8 + 2 * cl;
            float b0 = bias ? bias[cc]     : 0.f;
            float b1 = bias ? bias[cc + 1] : 0.f;
            float v0 = acc[mt][nt][0] + b0;
            float v1 = acc[mt][nt][1] + b1;
            float v2 = acc[mt][nt][2] + b0;
            float v3 = acc[mt][nt][3] + b1;
            if (GELU) {
                v0 = 0.5f * v0 * (1.f + erff(v0 * 0.70710678118654752f));
                v1 = 0.5f * v1 * (1.f + erff(v1 * 0.70710678118654752f));
                v2 = 0.5f * v2 * (1.f + erff(v2 * 0.70710678118654752f));
                v3 = 0.5f * v3 * (1.f + erff(v3 * 0.70710678118654752f));
            }
            if (CVT) { v0 = cvt_tf32(v0); v1 = cvt_tf32(v1); v2 = cvt_tf32(v2); v3 = cvt_tf32(v3); }
            *(float2*)(C + (size_t)r * N + cc)       = make_float2(v0, v1);
            *(float2*)(C + (size_t)(r + 8) * N + cc) = make_float2(v2, v3);
        }
    }
}

// ---------------- prep kernels ----------------
__global__ void cvtcopy_k(const float* __restrict__ src, float* __restrict__ dst)
{
    int i = (blockIdx.x * 256 + threadIdx.x) * 4;
    float4 v = *(const float4*)(src + i);
    v.x = cvt_tf32(v.x); v.y = cvt_tf32(v.y); v.z = cvt_tf32(v.z); v.w = cvt_tf32(v.w);
    *(float4*)(dst + i) = v;
}

__global__ void trcvt_k(const float* __restrict__ src, float* __restrict__ dst, int K, int N)
{
    __shared__ float t[32][33];
    int n0 = blockIdx.x * 32, k0 = blockIdx.y * 32;
    int tx = threadIdx.x, ty = threadIdx.y;
    #pragma unroll
    for (int r = ty; r < 32; r += 8)
        t[r][tx] = src[(size_t)(k0 + r) * N + n0 + tx];
    __syncthreads();
    #pragma unroll
    for (int r = ty; r < 32; r += 8)
        dst[(size_t)(n0 + r) * K + k0 + tx] = cvt_tf32(t[tx][r]);
}

__global__ void packT_k(const float* __restrict__ qmod_w, const float* __restrict__ kmod_w,
                        const float* __restrict__ cq_w,   const float* __restrict__ ck_w,
                        float* __restrict__ wcat)
{
    int idx = blockIdx.x * 256 + threadIdx.x;   // 384*1024
    int c = idx >> 10, k = idx & 1023;
    float v = 0.f;
    if      (c < 16)  v = qmod_w[k*Hh + c];
    else if (c < 32)  v = kmod_w[k*Hh + (c - 16)];
    else if (c < 160) v = cq_w[k*(Hh*CRc) + (c - 32)];
    else if (c < 288) v = ck_w[k*(Hh*CRc) + (c - 160)];
    wcat[(size_t)(1024 + c) * Dd + k] = cvt_tf32(v);
}

__global__ void biascat_k(const float* __restrict__ v_b, const float* __restrict__ qmod_b,
                          const float* __restrict__ kmod_b, float* __restrict__ bcat)
{
    int c = blockIdx.x * 256 + threadIdx.x;
    if (c >= VPW) return;
    float v = 0.f;
    if (c < 1024) v = v_b[c];
    else { int p = c - 1024; if (p < 16) v = qmod_b[p]; else if (p < 32) v = kmod_b[p - 16]; }
    bcat[c] = v;
}

// ---------------- pooled mean over S ----------------
__global__ void pool1_k(const float* __restrict__ x, float* __restrict__ pp)
{
    int idx = blockIdx.x * 256 + threadIdx.x;       // 0..2047 over (b,d)
    int sl  = blockIdx.y;                           // 0..15
    int b = idx >> 10, d = idx & 1023;
    const float* xp = x + (size_t)(b*Ss + sl*64)*Dd + d;
    float s0=0,s1=0,s2=0,s3=0;
    for (int q = 0; q < 64; q += 4) {
        s0 += xp[(size_t)(q+0)*Dd];
        s1 += xp[(size_t)(q+1)*Dd];
        s2 += xp[(size_t)(q+2)*Dd];
        s3 += xp[(size_t)(q+3)*Dd];
    }
    pp[sl*2048 + idx] = (s0+s1)+(s2+s3);
}

__global__ void pool2_k(const float* __restrict__ pp, float* __restrict__ pooled)
{
    int idx = blockIdx.x * 256 + threadIdx.x;
    float s = 0.f;
    #pragma unroll
    for (int q = 0; q < 16; q++) s += pp[q*2048 + idx];
    pooled[idx] = s * (1.f/Ss);
}

// ---------------- gating (straight-through top-k == softmax in fwd) ----------------
__global__ void __launch_bounds__(256) gating_k(const float* __restrict__ pooled,
    const float* __restrict__ gate_w, const float* __restrict__ gate_b,
    const float* __restrict__ mod_w,  const float* __restrict__ mod_b,
    const float* __restrict__ mod_basis, float* __restrict__ wts)
{
    int blk = blockIdx.x;
    int b = blk / Hh, h = blk % Hh;
    int tid = threadIdx.x, warp = tid >> 5, lane = tid & 31;
    __shared__ float ps[Dd];
    __shared__ float outs[24];
    __shared__ float gls[MMm];
    for (int q = tid; q < Dd; q += 256) ps[q] = pooled[b*Dd + q];
    __syncthreads();
    for (int o = warp; o < 24; o += 8) {
        const float* wcol; int stride; float bias;
        if (o < 16) { wcol = gate_w + h*MMm + o;      stride = Hh*MMm; bias = gate_b[h*MMm + o]; }
        else        { int r = o-16; wcol = mod_w + h*RMm + r; stride = Hh*RMm; bias = mod_b[h*RMm + r]; }
        float s = 0.f;
        for (int dI = lane; dI < Dd; dI += 32) s += ps[dI] * wcol[(size_t)dI * stride];
        #pragma unroll
        for (int off = 16; off; off >>= 1) s += __shfl_xor_sync(0xffffffffu, s, off);
        if (lane == 0) outs[o] = s + bias;
    }
    __syncthreads();
    if (tid < MMm) {
        float gl = outs[tid];
        #pragma unroll
        for (int r = 0; r < RMm; r++) gl += outs[16 + r] * mod_basis[(r*Hh + h)*MMm + tid];
        gls[tid] = gl;
    }
    __syncthreads();
    if (tid == 0) {
        float mx = -1e30f;
        for (int m = 0; m < MMm; m++) mx = fmaxf(mx, gls[m]);
        float e[MMm], sm = 0.f;
        for (int m = 0; m < MMm; m++) { e[m] = expf(gls[m] - mx); sm += e[m]; }
        float inv = 1.f / sm;
        for (int m = 0; m < MMm; m++) wts[(b*Hh + h)*MMm + m] = e[m] * inv;
    }
}

// ---------------- wave mask -> causal Toeplitz kernel row ----------------
__global__ void __launch_bounds__(256) wave_k(const float* __restrict__ wts,
    const float* __restrict__ freqs, const float* __restrict__ amps,
    const float* __restrict__ phases, float* __restrict__ ckr)
{
    int b = blockIdx.z, h = blockIdx.y;
    int d = blockIdx.x * 256 + threadIdx.x;
    __shared__ float fs[MMm*WWw*2], as_[MMm*WWw], ph_[MMm*WWw], ws[MMm];
    int t = threadIdx.x;
    fs[t] = freqs[h*MMm*WWw*2 + t];
    if (t < MMm*WWw) { as_[t] = amps[h*MMm*WWw + t]; ph_[t] = phases[h*MMm*WWw + t]; }
    if (t < MMm) ws[t] = wts[(b*Hh + h)*MMm + t];
    __syncthreads();
    float p1 = d * (1.f/Ss);
    float p2 = (d == 0) ? 0.f : sqrtf((float)d + 1e-6f) * 0.03125f;
    float kern = 0.f;
    #pragma unroll
    for (int m = 0; m < MMm; m++) {
        float acc = 0.f;
        #pragma unroll
        for (int w = 0; w < WWw; w++) {
            int iw = m*WWw + w;
            acc += as_[iw] * sinf(fs[iw*2+0]*p1 + fs[iw*2+1]*p2 + ph_[iw]);
        }
        kern += ws[m] * acc;
    }
    float dens = 1.f / (1.f + expf(-6.f * kern));
    float win  = expf(-(float)d * (float)d * (1.f/131072.f));
    ckr[(b*Hh + h)*Ss + d] = 3.f * dens * win;
}

// ---------------- flash attention ----------------
__global__ void __launch_bounds__(256) attn_k(const float* __restrict__ vp,
    const float* __restrict__ ckr, float* __restrict__ ctx)
{
    const int b = blockIdx.z, h = blockIdx.y;
    const int iBase = blockIdx.x * 8;
    const int tid = threadIdx.x, warp = tid >> 5, lane = tid & 31;
    const int i = iBase + warp;
    const float cmix = 0.0530330085889911f;   // MIX / sqrt(CR)

    __shared__ float ck_s[Ss];
    __shared__ float kc_s[64][CRc];
    __shared__ float km_s[64];
    __shared__ float p_s[8][64];

    for (int o = tid; o < Ss; o += 256) ck_s[o] = ckr[(b*Hh + h)*Ss + o];

    const float* vpB = vp + (size_t)(b*Ss) * VPW;
    float qcr[CRc];
    #pragma unroll
    for (int c = 0; c < CRc; c++) qcr[c] = vpB[(size_t)i*VPW + 1056 + h*CRc + c];
    const float qmi = vpB[(size_t)i*VPW + 1024 + h];

    float mrun = -1e30f, lrun = 0.f;
    float acc0 = 0.f, acc1 = 0.f;
    const int d0 = lane * 2;
    const int jEnd = iBase + 8;

    for (int jb = 0; jb < jEnd; jb += 64) {
        __syncthreads();
        {
            int idx = tid;
            #pragma unroll
            for (int g = 0; g < 2; g++, idx += 256) {
                int jj = idx >> 3, c = idx & 7;
                kc_s[jj][c] = vpB[(size_t)(jb + jj)*VPW + 1184 + h*CRc + c];
            }
            if (tid < 64) km_s[tid] = vpB[(size_t)(jb + tid)*VPW + 1040 + h];
        }
        __syncthreads();

        float s1 = -1e30f, s2 = -1e30f;
        {
            int j1 = jb + lane;
            if (j1 <= i) {
                float dot = 0.f;
                #pragma unroll
                for (int c = 0; c < CRc; c++) dot += qcr[c] * kc_s[lane][c];
                s1 = ck_s[i - j1] + qmi + km_s[lane] + cmix * dot;
            }
            int j2 = jb + lane + 32;
            if (j2 <= i) {
                float dot = 0.f;
                #pragma unroll
                for (int c = 0; c < CRc; c++) dot += qcr[c] * kc_s[lane + 32][c];
                s2 = ck_s[i - j2] + qmi + km_s[lane + 32] + cmix * dot;
            }
        }
        float cmax = fmaxf(s1, s2);
        #pragma unroll
        for (int o = 16; o; o >>= 1) cmax = fmaxf(cmax, __shfl_xor_sync(0xffffffffu, cmax, o));
        float mnew  = fmaxf(mrun, cmax);
        float scale = __expf(mrun - mnew);
        float p1 = __expf(s1 - mnew);
        float p2 = __expf(s2 - mnew);
        float ps = p1 + p2;
        #pragma unroll
        for (int o = 16; o; o >>= 1) ps += __shfl_xor_sync(0xffffffffu, ps, o);
        lrun = lrun * scale + ps;
        acc0 *= scale; acc1 *= scale;
        p_s[warp][lane] = p1; p_s[warp][lane + 32] = p2;
        __syncwarp();
        const float2* vrow = (const float2*)(vpB + (size_t)jb*VPW + h*HDd + d0);
        #pragma unroll 8
        for (int jj = 0; jj < 64; jj++) {
            float2 vv = vrow[(size_t)jj * (VPW/2)];
            float p = p_s[warp][jj];
            acc0 += p * vv.x; acc1 += p * vv.y;
        }
        __syncwarp();
        mrun = mnew;
    }
    float inv = 1.f / lrun;
    float2* orow = (float2*)(ctx + (size_t)(b*Ss + i)*Dd + h*HDd + d0);
    *orow = make_float2(cvt_tf32(acc0 * inv), cvt_tf32(acc1 * inv));
}

// ---------------- fused residual + LayerNorm (optional tf32 copy) ----------------
__global__ void __launch_bounds__(256) ln_k(const float* __restrict__ a,
    const float* __restrict__ r, const float* __restrict__ g,
    const float* __restrict__ bta, float* __restrict__ out, float* __restrict__ out2)
{
    int row = blockIdx.x;
    size_t base = (size_t)row * Dd;
    int tid = threadIdx.x;
    float vals[4], s = 0.f, s2 = 0.f;
    #pragma unroll
    for (int q = 0; q < 4; q++) {
        int idx = tid + q*256;
        float xv = a[base + idx] + r[base + idx];
        vals[q] = xv; s += xv; s2 += xv*xv;
    }
    __shared__ float red[64];
    #pragma unroll
    for (int o = 16; o; o >>= 1) {
        s  += __shfl_xor_sync(0xffffffffu, s,  o);
        s2 += __shfl_xor_sync(0xffffffffu, s2, o);
    }
    int warp = tid >> 5, lane = tid & 31;
    if (lane == 0) { red[warp] = s; red[32 + warp] = s2; }
    __syncthreads();
    if (warp == 0) {
        float a1 = (lane < 8) ? red[lane] : 0.f;
        float a2 = (lane < 8) ? red[32 + lane] : 0.f;
        #pragma unroll
        for (int o = 4; o; o >>= 1) {
            a1 += __shfl_xor_sync(0xffffffffu, a1, o);
            a2 += __shfl_xor_sync(0xffffffffu, a2, o);
        }
        if (lane == 0) { red[0] = a1; red[1] = a2; }
    }
    __syncthreads();
    float mean = red[0] * (1.f/Dd);
    float var  = red[1] * (1.f/Dd) - mean*mean;
    float rstd = rsqrtf(var + 1e-5f);
    #pragma unroll
    for (int q = 0; q < 4; q++) {
        int idx = tid + q*256;
        float o = (vals[q] - mean) * rstd * g[idx] + bta[idx];
        out[base + idx] = o;
        if (out2) out2[base + idx] = cvt_tf32(o);
    }
}

// ---------------- launch ----------------
extern "C" void kernel_launch(void* const* d_in, const int* in_sizes, int n_in,
                              void* d_out, int out_size)
{
    const float* x      = (const float*)d_in[0];
    const float* v_w    = (const float*)d_in[1];
    const float* v_b    = (const float*)d_in[2];
    const float* out_w  = (const float*)d_in[3];
    const float* out_b  = (const float*)d_in[4];
    const float* qmod_w = (const float*)d_in[5];
    const float* qmod_b = (const float*)d_in[6];
    const float* kmod_w = (const float*)d_in[7];
    const float* kmod_b = (const float*)d_in[8];
    const float* gate_w = (const float*)d_in[9];
    const float* gate_b = (const float*)d_in[10];
    const float* mod_w  = (const float*)d_in[11];
    const float* mod_b  = (const float*)d_in[12];
    const float* mod_basis = (const float*)d_in[13];
    const float* freqs  = (const float*)d_in[14];
    const float* amps   = (const float*)d_in[15];
    const float* phases = (const float*)d_in[16];
    const float* cq_w   = (const float*)d_in[17];
    const float* ck_w   = (const float*)d_in[18];
    const float* ffn_w1 = (const float*)d_in[19];
    const float* ffn_b1 = (const float*)d_in[20];
    const float* ffn_w2 = (const float*)d_in[21];
    const float* ffn_b2 = (const float*)d_in[22];
    const float* ln1_g  = (const float*)d_in[23];
    const float* ln1_b  = (const float*)d_in[24];
    const float* ln2_g  = (const float*)d_in[25];
    const float* ln2_b  = (const float*)d_in[26];
    float* out = (float*)d_out;

    float *pxc, *pwcat, *pbcat, *pvp, *powT, *pw1T, *pw2T, *ppp, *ppool,
          *pwts, *pck, *pctx, *pao, *ph, *phc, *pffn, *pf2;
    cudaGetSymbolAddress((void**)&pxc,  g_xc);
    cudaGetSymbolAddress((void**)&pwcat,g_wcat);
    cudaGetSymbolAddress((void**)&pbcat,g_bcat);
    cudaGetSymbolAddress((void**)&pvp,  g_vp);
    cudaGetSymbolAddress((void**)&powT, g_owT);
    cudaGetSymbolAddress((void**)&pw1T, g_w1T);
    cudaGetSymbolAddress((void**)&pw2T, g_w2T);
    cudaGetSymbolAddress((void**)&ppp,  g_pp);
    cudaGetSymbolAddress((void**)&ppool,g_pool);
    cudaGetSymbolAddress((void**)&pwts, g_wts);
    cudaGetSymbolAddress((void**)&pck,  g_ckr);
    cudaGetSymbolAddress((void**)&pctx, g_ctx);
    cudaGetSymbolAddress((void**)&pao,  g_ao);
    cudaGetSymbolAddress((void**)&ph,   g_h);
    cudaGetSymbolAddress((void**)&phc,  g_hc);
    cudaGetSymbolAddress((void**)&pffn, g_ffn);
    cudaGetSymbolAddress((void**)&pf2,  g_f2);

    // prep: tf32 x, transposed+rounded weights
    cvtcopy_k<<<(ROWS*Dd)/1024, 256>>>(x, pxc);
    trcvt_k<<<dim3(Dd/32, Dd/32), dim3(32,8)>>>(v_w, pwcat, Dd, Dd);
    packT_k<<<(384*Dd)/256, 256>>>(qmod_w, kmod_w, cq_w, ck_w, pwcat);
    biascat_k<<<6, 256>>>(v_b, qmod_b, kmod_b, pbcat);
    trcvt_k<<<dim3(Dd/32, Dd/32), dim3(32,8)>>>(out_w, powT, Dd, Dd);
    trcvt_k<<<dim3(FFD/32, Dd/32), dim3(32,8)>>>(ffn_w1, pw1T, Dd, FFD);
    trcvt_k<<<dim3(Dd/32, FFD/32), dim3(32,8)>>>(ffn_w2, pw2T, FFD, Dd);

    // fused v + proj GEMM
    gemm5<false,false><<<dim3(VPW/128, ROWS/128), 256>>>(pxc, pwcat, pbcat, pvp, ROWS, VPW, Dd);

    // gating path
    pool1_k<<<dim3(8,16), 256>>>(x, ppp);
    pool2_k<<<8, 256>>>(ppp, ppool);
    gating_k<<<Bb*Hh, 256>>>(ppool, gate_w, gate_b, mod_w, mod_b, mod_basis, pwts);
    wave_k<<<dim3(Ss/256, Hh, Bb), 256>>>(pwts, freqs, amps, phases, pck);

    // attention
    attn_k<<<dim3(Ss/8, Hh, Bb), 256>>>(pvp, pck, pctx);
    gemm5<false,false><<<dim3(Dd/128, ROWS/128), 256>>>(pctx, powT, out_b, pao, ROWS, Dd, Dd);

    // LN1 + FFN + LN2
    ln_k<<<ROWS, 256>>>(x, pao, ln1_g, ln1_b, ph, phc);
    gemm5<true,true ><<<dim3(FFD/128, ROWS/128), 256>>>(phc,  pw1T, ffn_b1, pffn, ROWS, FFD, Dd);
    gemm5<false,false><<<dim3(Dd/128, ROWS/128), 256>>>(pffn, pw2T, ffn_b2, pf2,  ROWS, Dd, FFD);
    ln_k<<<ROWS, 256>>>(ph, pf2, ln2_g, ln2_b, out, nullptr);
}

// round 5
// speedup vs baseline: 3.1807x; 1.4463x over previous
#include <cuda_runtime.h>
#include <cuda_fp16.h>
#include <math.h>
#include <stdint.h>

// ---------------- problem constants ----------------
#define Bb   2
#define Ss   1024
#define Dd   1024
#define Hh   16
#define HDd  64
#define MMm  16
#define WWw  8
#define RMm  8
#define CRc  8
#define FFD  4096
#define ROWS (Bb*Ss)          // 2048
#define VPW  1408             // fused v(1024) + proj(384) width

// ---------------- scratch (no allocations allowed) ----------------
__device__ __half g_xh   [ROWS*Dd];
__device__ __half g_wcat [VPW*Dd];       // [N=1408][K=1024] half, transposed v_w + packed proj
__device__ float  g_bcat [VPW];
__device__ float  g_vp   [ROWS*VPW];     // v | qm | km | qc | kc (fp32)
__device__ __half g_owT  [Dd*Dd];
__device__ __half g_w1T  [FFD*Dd];
__device__ __half g_w2T  [Dd*FFD];
__device__ __half g_ctxh [ROWS*Dd];
__device__ __half g_hch  [ROWS*Dd];
__device__ __half g_ffnh [ROWS*FFD];
__device__ float  g_pp   [16*ROWS];
__device__ float  g_pool [Bb*Dd];
__device__ float  g_wts  [Bb*Hh*MMm];
__device__ float  g_ckr  [Bb*Hh*Ss];
__device__ float  g_ao   [ROWS*Dd];
__device__ float  g_h    [ROWS*Dd];
__device__ float  g_f2   [ROWS*Dd];

// ---------------- helpers ----------------
__device__ __forceinline__ uint32_t smem_u32(const void* p) {
    uint32_t a;
    asm("{ .reg .u64 t; cvta.to.shared.u64 t, %1; cvt.u32.u64 %0, t; }" : "=r"(a) : "l"(p));
    return a;
}
__device__ __forceinline__ void mma_f16(float* c, const uint32_t* a, const uint32_t* b) {
    asm volatile(
        "mma.sync.aligned.m16n8k16.row.col.f32.f16.f16.f32 "
        "{%0,%1,%2,%3}, {%4,%5,%6,%7}, {%8,%9}, {%0,%1,%2,%3};"
        : "+f"(c[0]), "+f"(c[1]), "+f"(c[2]), "+f"(c[3])
        : "r"(a[0]), "r"(a[1]), "r"(a[2]), "r"(a[3]), "r"(b[0]), "r"(b[1]));
}
__device__ __forceinline__ void cpa16(uint32_t dst, const void* src) {
    asm volatile("cp.async.cg.shared.global [%0], [%1], 16;" :: "r"(dst), "l"(src));
}
#define CPA_COMMIT() asm volatile("cp.async.commit_group;" ::: "memory")

__device__ __forceinline__ void st2(float* p, float a, float b) { *(float2*)p = make_float2(a, b); }
__device__ __forceinline__ void st2(__half* p, float a, float b) { *(__half2*)p = __floats2half2_rn(a, b); }

// ---------------- fp16 tensor-core GEMM: C[M,N] = A[M,K] @ Bt[N,K]^T + bias ----
// A, Bt half, K-major. M,N multiples of 128, K multiple of 32.
// SMEM per stage: A 128 rows x 64B (K=32 halves) + B same = 16 KB; 3 stages.
// Swizzle: 16B unit u of row r stored at unit (u ^ ((r>>1)&3)) -> conflict-free
// for both cp.async stores and ldmatrix 8-row phases.
template<bool GELU, typename OT>
__global__ void __launch_bounds__(256, 2)
gemmh(const __half* __restrict__ A, const __half* __restrict__ Bt,
      const float* __restrict__ bias, OT* __restrict__ C,
      int M, int N, int K)
{
    __shared__ __align__(16) unsigned char smem[3 * 16384];
    const int tid = threadIdx.x, lane = tid & 31, warp = tid >> 5;
    const int wm = warp & 1, wn = warp >> 1;       // warp tile 64x32
    const int rr = lane >> 2, cl = lane & 3;
    const int m0 = blockIdx.y * 128, n0 = blockIdx.x * 128;
    const __half* Arow = A  + (size_t)m0 * K;
    const __half* Brow = Bt + (size_t)n0 * K;
    const uint32_t sbase = smem_u32(smem);
    const int T = K >> 5;

    float acc[4][4][4];
    #pragma unroll
    for (int mt = 0; mt < 4; mt++)
        #pragma unroll
        for (int nt = 0; nt < 4; nt++)
            #pragma unroll
            for (int q = 0; q < 4; q++) acc[mt][nt][q] = 0.f;

    auto stage = [&](int t) {
        const uint32_t sb = sbase + (t % 3) * 16384;
        const int k0 = t << 5;
        #pragma unroll
        for (int q = 0; q < 2; q++) {
            int ch = q * 256 + tid;                 // 0..511
            int row = ch >> 2, u = ch & 3;
            uint32_t off = row * 64 + (((u ^ ((row >> 1) & 3))) << 4);
            cpa16(sb + off,        Arow + (size_t)row * K + k0 + u * 8);
            cpa16(sb + 8192 + off, Brow + (size_t)row * K + k0 + u * 8);
        }
        CPA_COMMIT();
    };

    stage(0); stage(1);
    for (int t = 0; t < T; t++) {
        if (t < T - 1) asm volatile("cp.async.wait_group 1;" ::: "memory");
        else           asm volatile("cp.async.wait_group 0;" ::: "memory");
        __syncthreads();
        const uint32_t sA = sbase + (t % 3) * 16384;
        const uint32_t sB = sA + 8192;

        #pragma unroll
        for (int kk = 0; kk < 2; kk++) {
            const int u0 = kk * 2;
            uint32_t af[4][4], bf[4][2];
            #pragma unroll
            for (int mt = 0; mt < 4; mt++) {
                const int tr = wm * 64 + mt * 16;
                int row = tr + ((lane >> 3) & 1) * 8 + (lane & 7);
                int unit = u0 + (lane >> 4);
                uint32_t addr = sA + row * 64 + ((unit ^ ((row >> 1) & 3)) << 4);
                asm volatile("ldmatrix.sync.aligned.m8n8.x4.shared.b16 {%0,%1,%2,%3}, [%4];"
                             : "=r"(af[mt][0]), "=r"(af[mt][1]), "=r"(af[mt][2]), "=r"(af[mt][3])
                             : "r"(addr));
            }
            #pragma unroll
            for (int nt = 0; nt < 4; nt++) {
                const int nb = wn * 32 + nt * 8;
                int row = nb + (lane & 7);
                int unit = u0 + ((lane >> 3) & 1);
                uint32_t addr = sB + row * 64 + ((unit ^ ((row >> 1) & 3)) << 4);
                asm volatile("ldmatrix.sync.aligned.m8n8.x2.shared.b16 {%0,%1}, [%2];"
                             : "=r"(bf[nt][0]), "=r"(bf[nt][1]) : "r"(addr));
            }
            #pragma unroll
            for (int mt = 0; mt < 4; mt++)
                #pragma unroll
                for (int nt = 0; nt < 4; nt++)
                    mma_f16(acc[mt][nt], af[mt], bf[nt]);
        }
        __syncthreads();
        if (t + 2 < T) stage(t + 2);
    }

    // epilogue
    #pragma unroll
    for (int mt = 0; mt < 4; mt++) {
        #pragma unroll
        for (int nt = 0; nt < 4; nt++) {
            int r  = m0 + wm * 64 + mt * 16 + rr;
            int cc = n0 + wn * 32 + nt * 8 + 2 * cl;
            float b0 = bias ? bias[cc]     : 0.f;
            float b1 = bias ? bias[cc + 1] : 0.f;
            float v0 = acc[mt][nt][0] + b0;
            float v1 = acc[mt][nt][1] + b1;
            float v2 = acc[mt][nt][2] + b0;
            float v3 = acc[mt][nt][3] + b1;
            if (GELU) {
                v0 = 0.5f * v0 * (1.f + erff(v0 * 0.70710678118654752f));
                v1 = 0.5f * v1 * (1.f + erff(v1 * 0.70710678118654752f));
                v2 = 0.5f * v2 * (1.f + erff(v2 * 0.70710678118654752f));
                v3 = 0.5f * v3 * (1.f + erff(v3 * 0.70710678118654752f));
            }
            st2(C + (size_t)r * N + cc,       v0, v1);
            st2(C + (size_t)(r + 8) * N + cc, v2, v3);
        }
    }
}

// ---------------- prep kernels ----------------
__global__ void cvth_k(const float* __restrict__ src, __half* __restrict__ dst)
{
    int i = (blockIdx.x * 256 + threadIdx.x) * 4;
    float4 v = *(const float4*)(src + i);
    *(__half2*)(dst + i)     = __floats2half2_rn(v.x, v.y);
    *(__half2*)(dst + i + 2) = __floats2half2_rn(v.z, v.w);
}

__global__ void trcvt_k(const float* __restrict__ src, __half* __restrict__ dst, int K, int N)
{
    __shared__ float t[32][33];
    int n0 = blockIdx.x * 32, k0 = blockIdx.y * 32;
    int tx = threadIdx.x, ty = threadIdx.y;
    #pragma unroll
    for (int r = ty; r < 32; r += 8)
        t[r][tx] = src[(size_t)(k0 + r) * N + n0 + tx];
    __syncthreads();
    #pragma unroll
    for (int r = ty; r < 32; r += 8)
        dst[(size_t)(n0 + r) * K + k0 + tx] = __float2half_rn(t[tx][r]);
}

__global__ void packT_k(const float* __restrict__ qmod_w, const float* __restrict__ kmod_w,
                        const float* __restrict__ cq_w,   const float* __restrict__ ck_w,
                        __half* __restrict__ wcat)
{
    int idx = blockIdx.x * 256 + threadIdx.x;   // 384*1024
    int c = idx >> 10, k = idx & 1023;
    float v = 0.f;
    if      (c < 16)  v = qmod_w[k*Hh + c];
    else if (c < 32)  v = kmod_w[k*Hh + (c - 16)];
    else if (c < 160) v = cq_w[k*(Hh*CRc) + (c - 32)];
    else if (c < 288) v = ck_w[k*(Hh*CRc) + (c - 160)];
    wcat[(size_t)(1024 + c) * Dd + k] = __float2half_rn(v);
}

__global__ void biascat_k(const float* __restrict__ v_b, const float* __restrict__ qmod_b,
                          const float* __restrict__ kmod_b, float* __restrict__ bcat)
{
    int c = blockIdx.x * 256 + threadIdx.x;
    if (c >= VPW) return;
    float v = 0.f;
    if (c < 1024) v = v_b[c];
    else { int p = c - 1024; if (p < 16) v = qmod_b[p]; else if (p < 32) v = kmod_b[p - 16]; }
    bcat[c] = v;
}

// ---------------- pooled mean over S ----------------
__global__ void pool1_k(const float* __restrict__ x, float* __restrict__ pp)
{
    int idx = blockIdx.x * 256 + threadIdx.x;       // 0..2047 over (b,d)
    int sl  = blockIdx.y;                           // 0..15
    int b = idx >> 10, d = idx & 1023;
    const float* xp = x + (size_t)(b*Ss + sl*64)*Dd + d;
    float s0=0,s1=0,s2=0,s3=0;
    for (int q = 0; q < 64; q += 4) {
        s0 += xp[(size_t)(q+0)*Dd];
        s1 += xp[(size_t)(q+1)*Dd];
        s2 += xp[(size_t)(q+2)*Dd];
        s3 += xp[(size_t)(q+3)*Dd];
    }
    pp[sl*2048 + idx] = (s0+s1)+(s2+s3);
}

__global__ void pool2_k(const float* __restrict__ pp, float* __restrict__ pooled)
{
    int idx = blockIdx.x * 256 + threadIdx.x;
    float s = 0.f;
    #pragma unroll
    for (int q = 0; q < 16; q++) s += pp[q*2048 + idx];
    pooled[idx] = s * (1.f/Ss);
}

// ---------------- gating (straight-through top-k == softmax in fwd) ----------------
__global__ void __launch_bounds__(256) gating_k(const float* __restrict__ pooled,
    const float* __restrict__ gate_w, const float* __restrict__ gate_b,
    const float* __restrict__ mod_w,  const float* __restrict__ mod_b,
    const float* __restrict__ mod_basis, float* __restrict__ wts)
{
    int blk = blockIdx.x;
    int b = blk / Hh, h = blk % Hh;
    int tid = threadIdx.x, warp = tid >> 5, lane = tid & 31;
    __shared__ float ps[Dd];
    __shared__ float outs[24];
    __shared__ float gls[MMm];
    for (int q = tid; q < Dd; q += 256) ps[q] = pooled[b*Dd + q];
    __syncthreads();
    for (int o = warp; o < 24; o += 8) {
        const float* wcol; int stride; float bias;
        if (o < 16) { wcol = gate_w + h*MMm + o;      stride = Hh*MMm; bias = gate_b[h*MMm + o]; }
        else        { int r = o-16; wcol = mod_w + h*RMm + r; stride = Hh*RMm; bias = mod_b[h*RMm + r]; }
        float s = 0.f;
        for (int dI = lane; dI < Dd; dI += 32) s += ps[dI] * wcol[(size_t)dI * stride];
        #pragma unroll
        for (int off = 16; off; off >>= 1) s += __shfl_xor_sync(0xffffffffu, s, off);
        if (lane == 0) outs[o] = s + bias;
    }
    __syncthreads();
    if (tid < MMm) {
        float gl = outs[tid];
        #pragma unroll
        for (int r = 0; r < RMm; r++) gl += outs[16 + r] * mod_basis[(r*Hh + h)*MMm + tid];
        gls[tid] = gl;
    }
    __syncthreads();
    if (tid == 0) {
        float mx = -1e30f;
        for (int m = 0; m < MMm; m++) mx = fmaxf(mx, gls[m]);
        float e[MMm], sm = 0.f;
        for (int m = 0; m < MMm; m++) { e[m] = expf(gls[m] - mx); sm += e[m]; }
        float inv = 1.f / sm;
        for (int m = 0; m < MMm; m++) wts[(b*Hh + h)*MMm + m] = e[m] * inv;
    }
}

// ---------------- wave mask -> causal Toeplitz kernel row ----------------
__global__ void __launch_bounds__(256) wave_k(const float* __restrict__ wts,
    const float* __restrict__ freqs, const float* __restrict__ amps,
    const float* __restrict__ phases, float* __restrict__ ckr)
{
    int b = blockIdx.z, h = blockIdx.y;
    int d = blockIdx.x * 256 + threadIdx.x;
    __shared__ float fs[MMm*WWw*2], as_[MMm*WWw], ph_[MMm*WWw], ws[MMm];
    int t = threadIdx.x;
    fs[t] = freqs[h*MMm*WWw*2 + t];
    if (t < MMm*WWw) { as_[t] = amps[h*MMm*WWw + t]; ph_[t] = phases[h*MMm*WWw + t]; }
    if (t < MMm) ws[t] = wts[(b*Hh + h)*MMm + t];
    __syncthreads();
    float p1 = d * (1.f/Ss);
    float p2 = (d == 0) ? 0.f : sqrtf((float)d + 1e-6f) * 0.03125f;
    float kern = 0.f;
    #pragma unroll
    for (int m = 0; m < MMm; m++) {
        float acc = 0.f;
        #pragma unroll
        for (int w = 0; w < WWw; w++) {
            int iw = m*WWw + w;
            acc += as_[iw] * sinf(fs[iw*2+0]*p1 + fs[iw*2+1]*p2 + ph_[iw]);
        }
        kern += ws[m] * acc;
    }
    float dens = 1.f / (1.f + expf(-6.f * kern));
    float win  = expf(-(float)d * (float)d * (1.f/131072.f));
    ckr[(b*Hh + h)*Ss + d] = 3.f * dens * win;
}

// ---------------- flash attention: 32 queries/CTA, 4 per warp ----------------
__global__ void __launch_bounds__(256) attn_k(const float* __restrict__ vp,
    const float* __restrict__ ckr, __half* __restrict__ ctx)
{
    const int b = blockIdx.z, h = blockIdx.y;
    const int qBase = blockIdx.x * 32;
    const int tid = threadIdx.x, warp = tid >> 5, lane = tid & 31;
    const int i0 = qBase + warp * 4;
    const float cmix = 0.0530330085889911f;   // MIX / sqrt(CR)

    __shared__ float ck_s[Ss];
    __shared__ float kc_s[64][CRc];
    __shared__ float km_s[64];
    __shared__ float p_s[8][4][64];

    for (int o = tid; o < Ss; o += 256) ck_s[o] = ckr[(b*Hh + h)*Ss + o];

    const float* vpB = vp + (size_t)(b*Ss) * VPW;
    float qcr[4][CRc], qmi[4];
    #pragma unroll
    for (int q = 0; q < 4; q++) {
        #pragma unroll
        for (int c = 0; c < CRc; c++)
            qcr[q][c] = vpB[(size_t)(i0 + q)*VPW + 1056 + h*CRc + c];
        qmi[q] = vpB[(size_t)(i0 + q)*VPW + 1024 + h];
    }

    float mrun[4], lrun[4], acc0[4], acc1[4];
    #pragma unroll
    for (int q = 0; q < 4; q++) { mrun[q] = -1e30f; lrun[q] = 0.f; acc0[q] = 0.f; acc1[q] = 0.f; }

    const int d0 = lane * 2;
    const int jEnd = qBase + 32;

    for (int jb = 0; jb < jEnd; jb += 64) {
        __syncthreads();
        {
            int idx = tid;
            #pragma unroll
            for (int g = 0; g < 2; g++, idx += 256) {
                int jj = idx >> 3, c = idx & 7;
                kc_s[jj][c] = vpB[(size_t)(jb + jj)*VPW + 1184 + h*CRc + c];
            }
            if (tid < 64) km_s[tid] = vpB[(size_t)(jb + tid)*VPW + 1040 + h];
        }
        __syncthreads();

        float dA[4], dB[4];
        #pragma unroll
        for (int q = 0; q < 4; q++) { dA[q] = 0.f; dB[q] = 0.f; }
        #pragma unroll
        for (int c = 0; c < CRc; c++) {
            float k0 = kc_s[lane][c], k1 = kc_s[lane + 32][c];
            #pragma unroll
            for (int q = 0; q < 4; q++) { dA[q] += qcr[q][c] * k0; dB[q] += qcr[q][c] * k1; }
        }
        const float kmA = km_s[lane], kmB = km_s[lane + 32];
        const int j1 = jb + lane, j2 = jb + lane + 32;

        #pragma unroll
        for (int q = 0; q < 4; q++) {
            const int i = i0 + q;
            float s1 = (j1 <= i) ? ck_s[i - j1] + qmi[q] + kmA + cmix * dA[q] : -1e30f;
            float s2 = (j2 <= i) ? ck_s[i - j2] + qmi[q] + kmB + cmix * dB[q] : -1e30f;
            float cmax = fmaxf(s1, s2);
            #pragma unroll
            for (int o = 16; o; o >>= 1) cmax = fmaxf(cmax, __shfl_xor_sync(0xffffffffu, cmax, o));
            float mnew  = fmaxf(mrun[q], cmax);
            float scale = __expf(mrun[q] - mnew);
            float p1 = __expf(s1 - mnew);
            float p2 = __expf(s2 - mnew);
            float ps = p1 + p2;
            #pragma unroll
            for (int o = 16; o; o >>= 1) ps += __shfl_xor_sync(0xffffffffu, ps, o);
            lrun[q] = lrun[q] * scale + ps;
            acc0[q] *= scale; acc1[q] *= scale;
            p_s[warp][q][lane] = p1; p_s[warp][q][lane + 32] = p2;
            mrun[q] = mnew;
        }
        __syncwarp();
        const float2* vrow = (const float2*)(vpB + (size_t)jb*VPW + h*HDd + d0);
        #pragma unroll 4
        for (int jj = 0; jj < 64; jj++) {
            float2 vv = vrow[(size_t)jj * (VPW/2)];
            #pragma unroll
            for (int q = 0; q < 4; q++) {
                float p = p_s[warp][q][jj];
                acc0[q] += p * vv.x; acc1[q] += p * vv.y;
            }
        }
        __syncwarp();
    }
    #pragma unroll
    for (int q = 0; q < 4; q++) {
        float inv = 1.f / lrun[q];
        __half2* orow = (__half2*)(ctx + (size_t)(b*Ss + i0 + q)*Dd + h*HDd + d0);
        *orow = __floats2half2_rn(acc0[q] * inv, acc1[q] * inv);
    }
}

// ---------------- fused residual + LayerNorm (optional half copy) ----------------
__global__ void __launch_bounds__(256) ln_k(const float* __restrict__ a,
    const float* __restrict__ r, const float* __restrict__ g,
    const float* __restrict__ bta, float* __restrict__ out, __half* __restrict__ out2)
{
    int row = blockIdx.x;
    size_t base = (size_t)row * Dd;
    int tid = threadIdx.x;
    float vals[4], s = 0.f, s2 = 0.f;
    #pragma unroll
    for (int q = 0; q < 4; q++) {
        int idx = tid + q*256;
        float xv = a[base + idx] + r[base + idx];
        vals[q] = xv; s += xv; s2 += xv*xv;
    }
    __shared__ float red[64];
    #pragma unroll
    for (int o = 16; o; o >>= 1) {
        s  += __shfl_xor_sync(0xffffffffu, s,  o);
        s2 += __shfl_xor_sync(0xffffffffu, s2, o);
    }
    int warp = tid >> 5, lane = tid & 31;
    if (lane == 0) { red[warp] = s; red[32 + warp] = s2; }
    __syncthreads();
    if (warp == 0) {
        float a1 = (lane < 8) ? red[lane] : 0.f;
        float a2 = (lane < 8) ? red[32 + lane] : 0.f;
        #pragma unroll
        for (int o = 4; o; o >>= 1) {
            a1 += __shfl_xor_sync(0xffffffffu, a1, o);
            a2 += __shfl_xor_sync(0xffffffffu, a2, o);
        }
        if (lane == 0) { red[0] = a1; red[1] = a2; }
    }
    __syncthreads();
    float mean = red[0] * (1.f/Dd);
    float var  = red[1] * (1.f/Dd) - mean*mean;
    float rstd = rsqrtf(var + 1e-5f);
    #pragma unroll
    for (int q = 0; q < 4; q++) {
        int idx = tid + q*256;
        float o = (vals[q] - mean) * rstd * g[idx] + bta[idx];
        out[base + idx] = o;
        if (out2) out2[base + idx] = __float2half_rn(o);
    }
}

// ---------------- launch ----------------
extern "C" void kernel_launch(void* const* d_in, const int* in_sizes, int n_in,
                              void* d_out, int out_size)
{
    const float* x      = (const float*)d_in[0];
    const float* v_w    = (const float*)d_in[1];
    const float* v_b    = (const float*)d_in[2];
    const float* out_w  = (const float*)d_in[3];
    const float* out_b  = (const float*)d_in[4];
    const float* qmod_w = (const float*)d_in[5];
    const float* qmod_b = (const float*)d_in[6];
    const float* kmod_w = (const float*)d_in[7];
    const float* kmod_b = (const float*)d_in[8];
    const float* gate_w = (const float*)d_in[9];
    const float* gate_b = (const float*)d_in[10];
    const float* mod_w  = (const float*)d_in[11];
    const float* mod_b  = (const float*)d_in[12];
    const float* mod_basis = (const float*)d_in[13];
    const float* freqs  = (const float*)d_in[14];
    const float* amps   = (const float*)d_in[15];
    const float* phases = (const float*)d_in[16];
    const float* cq_w   = (const float*)d_in[17];
    const float* ck_w   = (const float*)d_in[18];
    const float* ffn_w1 = (const float*)d_in[19];
    const float* ffn_b1 = (const float*)d_in[20];
    const float* ffn_w2 = (const float*)d_in[21];
    const float* ffn_b2 = (const float*)d_in[22];
    const float* ln1_g  = (const float*)d_in[23];
    const float* ln1_b  = (const float*)d_in[24];
    const float* ln2_g  = (const float*)d_in[25];
    const float* ln2_b  = (const float*)d_in[26];
    float* out = (float*)d_out;

    __half *pxh, *pwcat, *powT, *pw1T, *pw2T, *pctxh, *phch, *pffnh;
    float *pbcat, *pvp, *ppp, *ppool, *pwts, *pck, *pao, *ph, *pf2;
    cudaGetSymbolAddress((void**)&pxh,  g_xh);
    cudaGetSymbolAddress((void**)&pwcat,g_wcat);
    cudaGetSymbolAddress((void**)&pbcat,g_bcat);
    cudaGetSymbolAddress((void**)&pvp,  g_vp);
    cudaGetSymbolAddress((void**)&powT, g_owT);
    cudaGetSymbolAddress((void**)&pw1T, g_w1T);
    cudaGetSymbolAddress((void**)&pw2T, g_w2T);
    cudaGetSymbolAddress((void**)&pctxh,g_ctxh);
    cudaGetSymbolAddress((void**)&phch, g_hch);
    cudaGetSymbolAddress((void**)&pffnh,g_ffnh);
    cudaGetSymbolAddress((void**)&ppp,  g_pp);
    cudaGetSymbolAddress((void**)&ppool,g_pool);
    cudaGetSymbolAddress((void**)&pwts, g_wts);
    cudaGetSymbolAddress((void**)&pck,  g_ckr);
    cudaGetSymbolAddress((void**)&pao,  g_ao);
    cudaGetSymbolAddress((void**)&ph,   g_h);
    cudaGetSymbolAddress((void**)&pf2,  g_f2);

    // prep: half x, transposed+converted weights
    cvth_k<<<(ROWS*Dd)/1024, 256>>>(x, pxh);
    trcvt_k<<<dim3(Dd/32, Dd/32), dim3(32,8)>>>(v_w, pwcat, Dd, Dd);
    packT_k<<<(384*Dd)/256, 256>>>(qmod_w, kmod_w, cq_w, ck_w, pwcat);
    biascat_k<<<6, 256>>>(v_b, qmod_b, kmod_b, pbcat);
    trcvt_k<<<dim3(Dd/32, Dd/32), dim3(32,8)>>>(out_w, powT, Dd, Dd);
    trcvt_k<<<dim3(FFD/32, Dd/32), dim3(32,8)>>>(ffn_w1, pw1T, Dd, FFD);
    trcvt_k<<<dim3(Dd/32, FFD/32), dim3(32,8)>>>(ffn_w2, pw2T, FFD, Dd);

    // fused v + proj GEMM
    gemmh<false,float><<<dim3(VPW/128, ROWS/128), 256>>>(pxh, pwcat, pbcat, pvp, ROWS, VPW, Dd);

    // gating path
    pool1_k<<<dim3(8,16), 256>>>(x, ppp);
    pool2_k<<<8, 256>>>(ppp, ppool);
    gating_k<<<Bb*Hh, 256>>>(ppool, gate_w, gate_b, mod_w, mod_b, mod_basis, pwts);
    wave_k<<<dim3(Ss/256, Hh, Bb), 256>>>(pwts, freqs, amps, phases, pck);

    // attention
    attn_k<<<dim3(Ss/32, Hh, Bb), 256>>>(pvp, pck, pctxh);
    gemmh<false,float><<<dim3(Dd/128, ROWS/128), 256>>>(pctxh, powT, out_b, pao, ROWS, Dd, Dd);

    // LN1 + FFN + LN2
    ln_k<<<ROWS, 256>>>(x, pao, ln1_g, ln1_b, ph, phch);
    gemmh<true,__half><<<dim3(FFD/128, ROWS/128), 256>>>(phch,  pw1T, ffn_b1, pffnh, ROWS, FFD, Dd);
    gemmh<false,float><<<dim3(Dd/128, ROWS/128), 256>>>(pffnh, pw2T, ffn_b2, pf2,  ROWS, Dd, FFD);
    ln_k<<<ROWS, 256>>>(ph, pf2, ln2_g, ln2_b, out, nullptr);
}

// round 6
// speedup vs baseline: 5.1585x; 1.6218x over previous
#include <cuda_runtime.h>
#include <cuda_fp16.h>
#include <math.h>
#include <stdint.h>

// ---------------- problem constants ----------------
#define Bb   2
#define Ss   1024
#define Dd   1024
#define Hh   16
#define HDd  64
#define MMm  16
#define WWw  8
#define RMm  8
#define CRc  8
#define FFD  4096
#define ROWS (Bb*Ss)          // 2048
#define VPW  1408             // fused v(1024) + proj(384) width

// ---------------- scratch ----------------
__device__ __half g_xh   [ROWS*Dd];
__device__ __half g_wcat [Dd*VPW];       // [K=1024][N=1408] half: v_w | qm | km | qc | kc
__device__ float  g_bcat [VPW];
__device__ float  g_vp   [ROWS*VPW];
__device__ __half g_owh  [Dd*Dd];        // [K][N] natural
__device__ __half g_w1h  [Dd*FFD];
__device__ __half g_w2h  [FFD*Dd];
__device__ __half g_ctxh [ROWS*Dd];
__device__ __half g_hch  [ROWS*Dd];
__device__ __half g_ffnh [ROWS*FFD];
__device__ float  g_pp   [64*2048];
__device__ float  g_pool [Bb*Dd];
__device__ float  g_wts  [Bb*Hh*MMm];
__device__ float  g_ckr  [Bb*Hh*Ss];
__device__ float  g_ao   [ROWS*Dd];
__device__ float  g_h    [ROWS*Dd];
__device__ float  g_f2   [ROWS*Dd];

// ---------------- helpers ----------------
__device__ __forceinline__ uint32_t smem_u32(const void* p) {
    uint32_t a;
    asm("{ .reg .u64 t; cvta.to.shared.u64 t, %1; cvt.u32.u64 %0, t; }" : "=r"(a) : "l"(p));
    return a;
}
__device__ __forceinline__ void mma_f16(float* c, const uint32_t* a, const uint32_t* b) {
    asm volatile(
        "mma.sync.aligned.m16n8k16.row.col.f32.f16.f16.f32 "
        "{%0,%1,%2,%3}, {%4,%5,%6,%7}, {%8,%9}, {%0,%1,%2,%3};"
        : "+f"(c[0]), "+f"(c[1]), "+f"(c[2]), "+f"(c[3])
        : "r"(a[0]), "r"(a[1]), "r"(a[2]), "r"(a[3]), "r"(b[0]), "r"(b[1]));
}
__device__ __forceinline__ void cpa16(uint32_t dst, const void* src) {
    asm volatile("cp.async.cg.shared.global [%0], [%1], 16;" :: "r"(dst), "l"(src));
}
#define CPA_COMMIT() asm volatile("cp.async.commit_group;" ::: "memory")
__device__ __forceinline__ uint32_t h2u(float a, float b) {
    __half2 h = __floats2half2_rn(a, b);
    return *(uint32_t*)&h;
}
__device__ __forceinline__ void st2(float* p, float a, float b) { *(float2*)p = make_float2(a, b); }
__device__ __forceinline__ void st2(__half* p, float a, float b) { *(__half2*)p = __floats2half2_rn(a, b); }

// ---------------- fp16 GEMM: C[M,N] = A[M,K] @ B[K,N] + bias ----------------
// A half K-major; B half row-major [K][N] (natural). M,N mult of 128, K mult of 32.
template<bool GELU, typename OT>
__global__ void __launch_bounds__(256, 2)
gemmh(const __half* __restrict__ A, const __half* __restrict__ B,
      const float* __restrict__ bias, OT* __restrict__ C,
      int M, int N, int K)
{
    __shared__ __align__(16) unsigned char smem[3 * 16384];
    const int tid = threadIdx.x, lane = tid & 31, warp = tid >> 5;
    const int wm = warp & 1, wn = warp >> 1;       // warp tile 64x32
    const int rr = lane >> 2, cl = lane & 3;
    const int m0 = blockIdx.y * 128, n0 = blockIdx.x * 128;
    const __half* Arow = A + (size_t)m0 * K;
    const __half* Bcol = B + n0;
    const uint32_t sbase = smem_u32(smem);
    const int T = K >> 5;

    float acc[4][4][4];
    #pragma unroll
    for (int mt = 0; mt < 4; mt++)
        #pragma unroll
        for (int nt = 0; nt < 4; nt++)
            #pragma unroll
            for (int q = 0; q < 4; q++) acc[mt][nt][q] = 0.f;

    auto stage = [&](int t) {
        const uint32_t sb = sbase + (t % 3) * 16384;
        const int k0 = t << 5;
        // A: 128 rows x 64B (4 units of 16B)
        #pragma unroll
        for (int q = 0; q < 2; q++) {
            int ch = q * 256 + tid;                 // 0..511
            int row = ch >> 2, u = ch & 3;
            uint32_t off = row * 64 + ((u ^ ((row >> 1) & 3)) << 4);
            cpa16(sb + off, Arow + (size_t)row * K + k0 + u * 8);
        }
        // B: 32 rows x 256B (16 units)
        #pragma unroll
        for (int q = 0; q < 2; q++) {
            int ch = q * 256 + tid;                 // 0..511
            int k = ch >> 4, u = ch & 15;
            uint32_t off = k * 256 + ((u ^ (k & 7)) << 4);
            cpa16(sb + 8192 + off, Bcol + (size_t)(k0 + k) * N + u * 8);
        }
        CPA_COMMIT();
    };

    stage(0); stage(1);
    for (int t = 0; t < T; t++) {
        if (t < T - 1) asm volatile("cp.async.wait_group 1;" ::: "memory");
        else           asm volatile("cp.async.wait_group 0;" ::: "memory");
        __syncthreads();
        const uint32_t sA = sbase + (t % 3) * 16384;
        const uint32_t sB = sA + 8192;

        #pragma unroll
        for (int kk = 0; kk < 2; kk++) {
            const int u0 = kk * 2;
            uint32_t af[4][4], bf[4][2];
            #pragma unroll
            for (int mt = 0; mt < 4; mt++) {
                const int tr = wm * 64 + mt * 16;
                int row = tr + ((lane >> 3) & 1) * 8 + (lane & 7);
                int unit = u0 + (lane >> 4);
                uint32_t addr = sA + row * 64 + ((unit ^ ((row >> 1) & 3)) << 4);
                asm volatile("ldmatrix.sync.aligned.m8n8.x4.shared.b16 {%0,%1,%2,%3}, [%4];"
                             : "=r"(af[mt][0]), "=r"(af[mt][1]), "=r"(af[mt][2]), "=r"(af[mt][3])
                             : "r"(addr));
            }
            #pragma unroll
            for (int nt = 0; nt < 4; nt++) {
                int rowk = kk * 16 + (lane & 15);
                uint32_t addr = sB + rowk * 256 + (((wn * 4 + nt) ^ (rowk & 7)) << 4);
                asm volatile("ldmatrix.sync.aligned.m8n8.x2.trans.shared.b16 {%0,%1}, [%2];"
                             : "=r"(bf[nt][0]), "=r"(bf[nt][1]) : "r"(addr));
            }
            #pragma unroll
            for (int mt = 0; mt < 4; mt++)
                #pragma unroll
                for (int nt = 0; nt < 4; nt++)
                    mma_f16(acc[mt][nt], af[mt], bf[nt]);
        }
        __syncthreads();
        if (t + 2 < T) stage(t + 2);
    }

    #pragma unroll
    for (int mt = 0; mt < 4; mt++) {
        #pragma unroll
        for (int nt = 0; nt < 4; nt++) {
            int r  = m0 + wm * 64 + mt * 16 + rr;
            int cc = n0 + wn * 32 + nt * 8 + 2 * cl;
            float b0 = bias ? bias[cc]     : 0.f;
            float b1 = bias ? bias[cc + 1] : 0.f;
            float v0 = acc[mt][nt][0] + b0;
            float v1 = acc[mt][nt][1] + b1;
            float v2 = acc[mt][nt][2] + b0;
            float v3 = acc[mt][nt][3] + b1;
            if (GELU) {
                v0 = 0.5f * v0 * (1.f + erff(v0 * 0.70710678118654752f));
                v1 = 0.5f * v1 * (1.f + erff(v1 * 0.70710678118654752f));
                v2 = 0.5f * v2 * (1.f + erff(v2 * 0.70710678118654752f));
                v3 = 0.5f * v3 * (1.f + erff(v3 * 0.70710678118654752f));
            }
            st2(C + (size_t)r * N + cc,       v0, v1);
            st2(C + (size_t)(r + 8) * N + cc, v2, v3);
        }
    }
}

// ---------------- prep kernels ----------------
__global__ void cvth_k(const float* __restrict__ src, __half* __restrict__ dst)
{
    int i = (blockIdx.x * 256 + threadIdx.x) * 4;
    float4 v = *(const float4*)(src + i);
    *(__half2*)(dst + i)     = __floats2half2_rn(v.x, v.y);
    *(__half2*)(dst + i + 2) = __floats2half2_rn(v.z, v.w);
}

// pack v_w | qmod | kmod | cq | ck into [K=1024][N=1408] half + bias cat
__global__ void wcat_k(const float* __restrict__ v_w, const float* __restrict__ v_b,
                       const float* __restrict__ qmod_w, const float* __restrict__ qmod_b,
                       const float* __restrict__ kmod_w, const float* __restrict__ kmod_b,
                       const float* __restrict__ cq_w,   const float* __restrict__ ck_w,
                       __half* __restrict__ wcat, float* __restrict__ bcat)
{
    int idx = blockIdx.x * 256 + threadIdx.x;          // over 1024*1408
    int k = idx / VPW, n = idx - k * VPW;
    float v = 0.f;
    if      (n < 1024) v = v_w[k*1024 + n];
    else {
        int c = n - 1024;
        if      (c < 16)  v = qmod_w[k*Hh + c];
        else if (c < 32)  v = kmod_w[k*Hh + (c - 16)];
        else if (c < 160) v = cq_w[k*(Hh*CRc) + (c - 32)];
        else if (c < 288) v = ck_w[k*(Hh*CRc) + (c - 160)];
    }
    wcat[idx] = __float2half_rn(v);
    if (idx < VPW) {
        float bv = 0.f;
        if (idx < 1024) bv = v_b[idx];
        else { int p = idx - 1024; if (p < 16) bv = qmod_b[p]; else if (p < 32) bv = kmod_b[p - 16]; }
        bcat[idx] = bv;
    }
}

// ---------------- pooled mean over S ----------------
__global__ void pool1_k(const float* __restrict__ x, float* __restrict__ pp)
{
    int idx = blockIdx.x * 256 + threadIdx.x;       // 0..2047 over (b,d)
    int sl  = blockIdx.y;                           // 0..63
    int b = idx >> 10, d = idx & 1023;
    const float* xp = x + (size_t)(b*Ss + sl*16)*Dd + d;
    float s0=0,s1=0;
    #pragma unroll
    for (int q = 0; q < 16; q += 2) {
        s0 += xp[(size_t)(q+0)*Dd];
        s1 += xp[(size_t)(q+1)*Dd];
    }
    pp[sl*2048 + idx] = s0+s1;
}

__global__ void pool2_k(const float* __restrict__ pp, float* __restrict__ pooled)
{
    int idx = blockIdx.x * 256 + threadIdx.x;
    float s = 0.f;
    #pragma unroll
    for (int q = 0; q < 64; q++) s += pp[q*2048 + idx];
    pooled[idx] = s * (1.f/Ss);
}

// ---------------- gating ----------------
__global__ void __launch_bounds__(256) gating_k(const float* __restrict__ pooled,
    const float* __restrict__ gate_w, const float* __restrict__ gate_b,
    const float* __restrict__ mod_w,  const float* __restrict__ mod_b,
    const float* __restrict__ mod_basis, float* __restrict__ wts)
{
    int blk = blockIdx.x;
    int b = blk / Hh, h = blk % Hh;
    int tid = threadIdx.x, warp = tid >> 5, lane = tid & 31;
    __shared__ float ps[Dd];
    __shared__ float outs[24];
    __shared__ float gls[MMm];
    for (int q = tid; q < Dd; q += 256) ps[q] = pooled[b*Dd + q];
    __syncthreads();
    for (int o = warp; o < 24; o += 8) {
        const float* wcol; int stride; float bias;
        if (o < 16) { wcol = gate_w + h*MMm + o;      stride = Hh*MMm; bias = gate_b[h*MMm + o]; }
        else        { int r = o-16; wcol = mod_w + h*RMm + r; stride = Hh*RMm; bias = mod_b[h*RMm + r]; }
        float s = 0.f;
        for (int dI = lane; dI < Dd; dI += 32) s += ps[dI] * wcol[(size_t)dI * stride];
        #pragma unroll
        for (int off = 16; off; off >>= 1) s += __shfl_xor_sync(0xffffffffu, s, off);
        if (lane == 0) outs[o] = s + bias;
    }
    __syncthreads();
    if (tid < MMm) {
        float gl = outs[tid];
        #pragma unroll
        for (int r = 0; r < RMm; r++) gl += outs[16 + r] * mod_basis[(r*Hh + h)*MMm + tid];
        gls[tid] = gl;
    }
    __syncthreads();
    if (tid == 0) {
        float mx = -1e30f;
        for (int m = 0; m < MMm; m++) mx = fmaxf(mx, gls[m]);
        float e[MMm], sm = 0.f;
        for (int m = 0; m < MMm; m++) { e[m] = expf(gls[m] - mx); sm += e[m]; }
        float inv = 1.f / sm;
        for (int m = 0; m < MMm; m++) wts[(b*Hh + h)*MMm + m] = e[m] * inv;
    }
}

// ---------------- wave mask -> causal Toeplitz row ----------------
__global__ void __launch_bounds__(256) wave_k(const float* __restrict__ wts,
    const float* __restrict__ freqs, const float* __restrict__ amps,
    const float* __restrict__ phases, float* __restrict__ ckr)
{
    int b = blockIdx.z, h = blockIdx.y;
    int d = blockIdx.x * 256 + threadIdx.x;
    __shared__ float fs[MMm*WWw*2], as_[MMm*WWw], ph_[MMm*WWw], ws[MMm];
    int t = threadIdx.x;
    fs[t] = freqs[h*MMm*WWw*2 + t];
    if (t < MMm*WWw) { as_[t] = amps[h*MMm*WWw + t]; ph_[t] = phases[h*MMm*WWw + t]; }
    if (t < MMm) ws[t] = wts[(b*Hh + h)*MMm + t];
    __syncthreads();
    float p1 = d * (1.f/Ss);
    float p2 = (d == 0) ? 0.f : sqrtf((float)d + 1e-6f) * 0.03125f;
    float kern = 0.f;
    #pragma unroll
    for (int m = 0; m < MMm; m++) {
        float acc = 0.f;
        #pragma unroll
        for (int w = 0; w < WWw; w++) {
            int iw = m*WWw + w;
            acc += as_[iw] * sinf(fs[iw*2+0]*p1 + fs[iw*2+1]*p2 + ph_[iw]);
        }
        kern += ws[m] * acc;
    }
    float dens = 1.f / (1.f + expf(-6.f * kern));
    float win  = expf(-(float)d * (float)d * (1.f/131072.f));
    ckr[(b*Hh + h)*Ss + d] = 3.f * dens * win;
}

// ---------------- flash attention, tensor-core PV ----------------
// CTA: 64 queries, 4 warps (warp w -> rows 16w..16w+15). j-blocks of 64.
// content+qm+km via one k16 mma (qc'=[cmix*qc,1,qm], kc'=[kc,km,1]); Toeplitz added
// elementwise in C-fragment layout; P C-frags == PV A-frags (no shuffle).
__global__ void __launch_bounds__(128) attn_k(const float* __restrict__ vp,
    const float* __restrict__ ckr, __half* __restrict__ ctx)
{
    const int b = blockIdx.z, h = blockIdx.y;
    const int qb = (gridDim.x - 1 - blockIdx.x) * 64;     // big tiles launch first
    const int tid = threadIdx.x, warp = tid >> 5, lane = tid & 31;
    const int g = lane >> 2, c2 = (lane & 3) * 2;

    __shared__ float  ck_s[Ss];
    __shared__ __align__(16) __half vts[64 * 68];   // V^T: [d][j], row stride 68 halves
    __shared__ __align__(16) __half kcs[64 * 18];   // kc': [j][16], row stride 18 halves

    for (int o = tid; o < Ss; o += 128) ck_s[o] = ckr[(b*Hh + h)*Ss + o];

    const float* vpB = vp + (size_t)(b*Ss) * VPW;
    const float cmix = 0.0530330085889911f;

    // qc' A-fragment (constant across j-blocks)
    const int i_lo = qb + warp*16 + g, i_hi = i_lo + 8;
    uint32_t aq[4];
    {
        float qlo0 = cmix * vpB[(size_t)i_lo*VPW + 1056 + h*CRc + c2];
        float qlo1 = cmix * vpB[(size_t)i_lo*VPW + 1056 + h*CRc + c2 + 1];
        float qhi0 = cmix * vpB[(size_t)i_hi*VPW + 1056 + h*CRc + c2];
        float qhi1 = cmix * vpB[(size_t)i_hi*VPW + 1056 + h*CRc + c2 + 1];
        aq[0] = h2u(qlo0, qlo1);
        aq[1] = h2u(qhi0, qhi1);
        if ((lane & 3) == 0) {
            aq[2] = h2u(1.f, vpB[(size_t)i_lo*VPW + 1024 + h]);
            aq[3] = h2u(1.f, vpB[(size_t)i_hi*VPW + 1024 + h]);
        } else { aq[2] = 0; aq[3] = 0; }
    }

    float m_lo = -1e30f, m_hi = -1e30f, l_lo = 0.f, l_hi = 0.f;
    float o_[8][4];
    #pragma unroll
    for (int nt = 0; nt < 8; nt++)
        #pragma unroll
        for (int q = 0; q < 4; q++) o_[nt][q] = 0.f;

    for (int jb = 0; jb <= qb; jb += 64) {
        __syncthreads();
        // stage kc' [64][16] halves (row stride 18)
        {
            int j = tid >> 1, sub = tid & 1;
            uint32_t* dst = (uint32_t*)((char*)kcs + j*36 + sub*16);
            if (sub == 0) {
                const float* kc = vpB + (size_t)(jb + j)*VPW + 1184 + h*CRc;
                dst[0] = h2u(kc[0], kc[1]); dst[1] = h2u(kc[2], kc[3]);
                dst[2] = h2u(kc[4], kc[5]); dst[3] = h2u(kc[6], kc[7]);
            } else {
                float km = vpB[(size_t)(jb + j)*VPW + 1040 + h];
                dst[0] = h2u(km, 1.f); dst[1] = 0; dst[2] = 0; dst[3] = 0;
            }
        }
        // stage V^T [d][j]
        #pragma unroll 8
        for (int it = 0; it < 32; it++) {
            int idx = it * 128 + tid;
            int j = idx >> 6, d = idx & 63;
            float v = vpB[(size_t)(jb + j)*VPW + h*HDd + d];
            vts[d*68 + j] = __float2half_rn(v);
        }
        __syncthreads();

        // scores: content mma + Toeplitz
        float s[8][4];
        #pragma unroll
        for (int nt = 0; nt < 8; nt++) {
            s[nt][0] = s[nt][1] = s[nt][2] = s[nt][3] = 0.f;
            uint32_t kb[2];
            const char* base = (const char*)kcs + (nt*8 + g)*36 + (lane & 3)*4;
            kb[0] = *(const uint32_t*)(base);
            kb[1] = *(const uint32_t*)(base + 16);
            mma_f16(s[nt], aq, kb);
        }
        const bool diag = (jb == qb);
        const int irl = warp*16 + g, irh = irl + 8;       // i relative to qb
        #pragma unroll
        for (int nt = 0; nt < 8; nt++) {
            int j0 = nt*8 + c2;                            // j relative to jb
            if (!diag) {
                int d0 = (i_lo - jb) - j0;
                s[nt][0] += ck_s[d0];
                s[nt][1] += ck_s[d0 - 1];
                s[nt][2] += ck_s[d0 + 8];
                s[nt][3] += ck_s[d0 + 7];
            } else {
                s[nt][0] = (j0     <= irl) ? s[nt][0] + ck_s[irl - j0]     : -1e30f;
                s[nt][1] = (j0 + 1 <= irl) ? s[nt][1] + ck_s[irl - j0 - 1] : -1e30f;
                s[nt][2] = (j0     <= irh) ? s[nt][2] + ck_s[irh - j0]     : -1e30f;
                s[nt][3] = (j0 + 1 <= irh) ? s[nt][3] + ck_s[irh - j0 - 1] : -1e30f;
            }
        }
        // online softmax (rows lo: s[.][0..1], hi: s[.][2..3]); reduce over 4-lane group
        float mx_lo = -1e30f, mx_hi = -1e30f;
        #pragma unroll
        for (int nt = 0; nt < 8; nt++) {
            mx_lo = fmaxf(mx_lo, fmaxf(s[nt][0], s[nt][1]));
            mx_hi = fmaxf(mx_hi, fmaxf(s[nt][2], s[nt][3]));
        }
        mx_lo = fmaxf(mx_lo, __shfl_xor_sync(0xffffffffu, mx_lo, 1));
        mx_lo = fmaxf(mx_lo, __shfl_xor_sync(0xffffffffu, mx_lo, 2));
        mx_hi = fmaxf(mx_hi, __shfl_xor_sync(0xffffffffu, mx_hi, 1));
        mx_hi = fmaxf(mx_hi, __shfl_xor_sync(0xffffffffu, mx_hi, 2));
        float mn_lo = fmaxf(m_lo, mx_lo), mn_hi = fmaxf(m_hi, mx_hi);
        float sc_lo = __expf(m_lo - mn_lo), sc_hi = __expf(m_hi - mn_hi);
        float p[8][4], sum_lo = 0.f, sum_hi = 0.f;
        #pragma unroll
        for (int nt = 0; nt < 8; nt++) {
            p[nt][0] = __expf(s[nt][0] - mn_lo);
            p[nt][1] = __expf(s[nt][1] - mn_lo);
            p[nt][2] = __expf(s[nt][2] - mn_hi);
            p[nt][3] = __expf(s[nt][3] - mn_hi);
            sum_lo += p[nt][0] + p[nt][1];
            sum_hi += p[nt][2] + p[nt][3];
        }
        sum_lo += __shfl_xor_sync(0xffffffffu, sum_lo, 1);
        sum_lo += __shfl_xor_sync(0xffffffffu, sum_lo, 2);
        sum_hi += __shfl_xor_sync(0xffffffffu, sum_hi, 1);
        sum_hi += __shfl_xor_sync(0xffffffffu, sum_hi, 2);
        l_lo = l_lo * sc_lo + sum_lo;  m_lo = mn_lo;
        l_hi = l_hi * sc_hi + sum_hi;  m_hi = mn_hi;
        #pragma unroll
        for (int nt = 0; nt < 8; nt++) {
            o_[nt][0] *= sc_lo; o_[nt][1] *= sc_lo;
            o_[nt][2] *= sc_hi; o_[nt][3] *= sc_hi;
        }
        // PV: P C-frags -> A-frags, V^T b-frags from smem
        #pragma unroll
        for (int kt = 0; kt < 4; kt++) {
            uint32_t pa[4];
            pa[0] = h2u(p[2*kt][0],   p[2*kt][1]);
            pa[1] = h2u(p[2*kt][2],   p[2*kt][3]);
            pa[2] = h2u(p[2*kt+1][0], p[2*kt+1][1]);
            pa[3] = h2u(p[2*kt+1][2], p[2*kt+1][3]);
            #pragma unroll
            for (int nt = 0; nt < 8; nt++) {
                uint32_t vb[2];
                const char* base = (const char*)vts + ((nt*8 + g)*68 + kt*16 + c2)*2;
                vb[0] = *(const uint32_t*)(base);
                vb[1] = *(const uint32_t*)(base + 16);
                mma_f16(o_[nt], pa, vb);
            }
        }
    }

    float inv_lo = 1.f / l_lo, inv_hi = 1.f / l_hi;
    #pragma unroll
    for (int nt = 0; nt < 8; nt++) {
        __half2* plo = (__half2*)(ctx + (size_t)(b*Ss + i_lo)*Dd + h*HDd + nt*8 + c2);
        __half2* phi = (__half2*)(ctx + (size_t)(b*Ss + i_hi)*Dd + h*HDd + nt*8 + c2);
        *plo = __floats2half2_rn(o_[nt][0]*inv_lo, o_[nt][1]*inv_lo);
        *phi = __floats2half2_rn(o_[nt][2]*inv_hi, o_[nt][3]*inv_hi);
    }
}

// ---------------- fused residual + LayerNorm ----------------
__global__ void __launch_bounds__(256) ln_k(const float* __restrict__ a,
    const float* __restrict__ r, const float* __restrict__ g,
    const float* __restrict__ bta, float* __restrict__ out, __half* __restrict__ out2)
{
    int row = blockIdx.x;
    size_t base = (size_t)row * Dd;
    int tid = threadIdx.x;
    float vals[4], s = 0.f, s2 = 0.f;
    #pragma unroll
    for (int q = 0; q < 4; q++) {
        int idx = tid + q*256;
        float xv = a[base + idx] + r[base + idx];
        vals[q] = xv; s += xv; s2 += xv*xv;
    }
    __shared__ float red[64];
    #pragma unroll
    for (int o = 16; o; o >>= 1) {
        s  += __shfl_xor_sync(0xffffffffu, s,  o);
        s2 += __shfl_xor_sync(0xffffffffu, s2, o);
    }
    int warp = tid >> 5, lane = tid & 31;
    if (lane == 0) { red[warp] = s; red[32 + warp] = s2; }
    __syncthreads();
    if (warp == 0) {
        float a1 = (lane < 8) ? red[lane] : 0.f;
        float a2 = (lane < 8) ? red[32 + lane] : 0.f;
        #pragma unroll
        for (int o = 4; o; o >>= 1) {
            a1 += __shfl_xor_sync(0xffffffffu, a1, o);
            a2 += __shfl_xor_sync(0xffffffffu, a2, o);
        }
        if (lane == 0) { red[0] = a1; red[1] = a2; }
    }
    __syncthreads();
    float mean = red[0] * (1.f/Dd);
    float var  = red[1] * (1.f/Dd) - mean*mean;
    float rstd = rsqrtf(var + 1e-5f);
    #pragma unroll
    for (int q = 0; q < 4; q++) {
        int idx = tid + q*256;
        float o = (vals[q] - mean) * rstd * g[idx] + bta[idx];
        out[base + idx] = o;
        if (out2) out2[base + idx] = __float2half_rn(o);
    }
}

// ---------------- launch ----------------
extern "C" void kernel_launch(void* const* d_in, const int* in_sizes, int n_in,
                              void* d_out, int out_size)
{
    const float* x      = (const float*)d_in[0];
    const float* v_w    = (const float*)d_in[1];
    const float* v_b    = (const float*)d_in[2];
    const float* out_w  = (const float*)d_in[3];
    const float* out_b  = (const float*)d_in[4];
    const float* qmod_w = (const float*)d_in[5];
    const float* qmod_b = (const float*)d_in[6];
    const float* kmod_w = (const float*)d_in[7];
    const float* kmod_b = (const float*)d_in[8];
    const float* gate_w = (const float*)d_in[9];
    const float* gate_b = (const float*)d_in[10];
    const float* mod_w  = (const float*)d_in[11];
    const float* mod_b  = (const float*)d_in[12];
    const float* mod_basis = (const float*)d_in[13];
    const float* freqs  = (const float*)d_in[14];
    const float* amps   = (const float*)d_in[15];
    const float* phases = (const float*)d_in[16];
    const float* cq_w   = (const float*)d_in[17];
    const float* ck_w   = (const float*)d_in[18];
    const float* ffn_w1 = (const float*)d_in[19];
    const float* ffn_b1 = (const float*)d_in[20];
    const float* ffn_w2 = (const float*)d_in[21];
    const float* ffn_b2 = (const float*)d_in[22];
    const float* ln1_g  = (const float*)d_in[23];
    const float* ln1_b  = (const float*)d_in[24];
    const float* ln2_g  = (const float*)d_in[25];
    const float* ln2_b  = (const float*)d_in[26];
    float* out = (float*)d_out;

    __half *pxh, *pwcat, *powh, *pw1h, *pw2h, *pctxh, *phch, *pffnh;
    float *pbcat, *pvp, *ppp, *ppool, *pwts, *pck, *pao, *ph, *pf2;
    cudaGetSymbolAddress((void**)&pxh,  g_xh);
    cudaGetSymbolAddress((void**)&pwcat,g_wcat);
    cudaGetSymbolAddress((void**)&pbcat,g_bcat);
    cudaGetSymbolAddress((void**)&pvp,  g_vp);
    cudaGetSymbolAddress((void**)&powh, g_owh);
    cudaGetSymbolAddress((void**)&pw1h, g_w1h);
    cudaGetSymbolAddress((void**)&pw2h, g_w2h);
    cudaGetSymbolAddress((void**)&pctxh,g_ctxh);
    cudaGetSymbolAddress((void**)&phch, g_hch);
    cudaGetSymbolAddress((void**)&pffnh,g_ffnh);
    cudaGetSymbolAddress((void**)&ppp,  g_pp);
    cudaGetSymbolAddress((void**)&ppool,g_pool);
    cudaGetSymbolAddress((void**)&pwts, g_wts);
    cudaGetSymbolAddress((void**)&pck,  g_ckr);
    cudaGetSymbolAddress((void**)&pao,  g_ao);
    cudaGetSymbolAddress((void**)&ph,   g_h);
    cudaGetSymbolAddress((void**)&pf2,  g_f2);

    // prep: half conversions in natural layouts (no transposes)
    cvth_k<<<(ROWS*Dd)/1024, 256>>>(x, pxh);
    wcat_k<<<(Dd*VPW)/256, 256>>>(v_w, v_b, qmod_w, qmod_b, kmod_w, kmod_b, cq_w, ck_w, pwcat, pbcat);
    cvth_k<<<(Dd*Dd)/1024, 256>>>(out_w, powh);
    cvth_k<<<(Dd*FFD)/1024, 256>>>(ffn_w1, pw1h);
    cvth_k<<<(FFD*Dd)/1024, 256>>>(ffn_w2, pw2h);

    // fused v + proj GEMM
    gemmh<false,float><<<dim3(VPW/128, ROWS/128), 256>>>(pxh, pwcat, pbcat, pvp, ROWS, VPW, Dd);

    // gating path
    pool1_k<<<dim3(8,64), 256>>>(x, ppp);
    pool2_k<<<8, 256>>>(ppp, ppool);
    gating_k<<<Bb*Hh, 256>>>(ppool, gate_w, gate_b, mod_w, mod_b, mod_basis, pwts);
    wave_k<<<dim3(Ss/256, Hh, Bb), 256>>>(pwts, freqs, amps, phases, pck);

    // attention (tensor-core PV)
    attn_k<<<dim3(Ss/64, Hh, Bb), 128>>>(pvp, pck, pctxh);
    gemmh<false,float><<<dim3(Dd/128, ROWS/128), 256>>>(pctxh, powh, out_b, pao, ROWS, Dd, Dd);

    // LN1 + FFN + LN2
    ln_k<<<ROWS, 256>>>(x, pao, ln1_g, ln1_b, ph, phch);
    gemmh<true,__half><<<dim3(FFD/128, ROWS/128), 256>>>(phch,  pw1h, ffn_b1, pffnh, ROWS, FFD, Dd);
    gemmh<false,float><<<dim3(Dd/128, ROWS/128), 256>>>(pffnh, pw2h, ffn_b2, pf2,  ROWS, Dd, FFD);
    ln_k<<<ROWS, 256>>>(ph, pf2, ln2_g, ln2_b, out, nullptr);
}

// round 7
// speedup vs baseline: 5.1661x; 1.0015x over previous
#include <cuda_runtime.h>
#include <cuda_fp16.h>
#include <math.h>
#include <stdint.h>

// ---------------- problem constants ----------------
#define Bb   2
#define Ss   1024
#define Dd   1024
#define Hh   16
#define HDd  64
#define MMm  16
#define WWw  8
#define RMm  8
#define CRc  8
#define FFD  4096
#define ROWS (Bb*Ss)          // 2048
#define VPW  1408             // fused v(1024) + proj(384) width

// ---------------- scratch ----------------
__device__ __half g_xh   [ROWS*Dd];
__device__ __half g_wcat [Dd*VPW];       // [K=1024][N=1408] half: v_w | qm | km | qc | kc
__device__ float  g_bcat [VPW];
__device__ __half g_vph  [ROWS*VPW];     // half vp: v | qm | km | qc | kc
__device__ __half g_owh  [Dd*Dd];
__device__ __half g_w1h  [Dd*FFD];
__device__ __half g_w2h  [FFD*Dd];
__device__ __half g_ctxh [ROWS*Dd];
__device__ __half g_hch  [ROWS*Dd];
__device__ __half g_ffnh [ROWS*FFD];
__device__ float  g_pp   [64*2048];
__device__ float  g_pool [Bb*Dd];
__device__ float  g_wts  [Bb*Hh*MMm];
__device__ float  g_ckr  [Bb*Hh*Ss];
__device__ float  g_ao   [ROWS*Dd];
__device__ float  g_h    [ROWS*Dd];
__device__ float  g_f2   [ROWS*Dd];

// ---------------- helpers ----------------
__device__ __forceinline__ uint32_t smem_u32(const void* p) {
    uint32_t a;
    asm("{ .reg .u64 t; cvta.to.shared.u64 t, %1; cvt.u32.u64 %0, t; }" : "=r"(a) : "l"(p));
    return a;
}
__device__ __forceinline__ void mma_f16(float* c, const uint32_t* a, const uint32_t* b) {
    asm volatile(
        "mma.sync.aligned.m16n8k16.row.col.f32.f16.f16.f32 "
        "{%0,%1,%2,%3}, {%4,%5,%6,%7}, {%8,%9}, {%0,%1,%2,%3};"
        : "+f"(c[0]), "+f"(c[1]), "+f"(c[2]), "+f"(c[3])
        : "r"(a[0]), "r"(a[1]), "r"(a[2]), "r"(a[3]), "r"(b[0]), "r"(b[1]));
}
__device__ __forceinline__ void cpa16(uint32_t dst, const void* src) {
    asm volatile("cp.async.cg.shared.global [%0], [%1], 16;" :: "r"(dst), "l"(src));
}
#define CPA_COMMIT() asm volatile("cp.async.commit_group;" ::: "memory")
__device__ __forceinline__ uint32_t h2u(float a, float b) {
    __half2 h = __floats2half2_rn(a, b);
    return *(uint32_t*)&h;
}
__device__ __forceinline__ void st2(float* p, float a, float b) { *(float2*)p = make_float2(a, b); }
__device__ __forceinline__ void st2(__half* p, float a, float b) { *(__half2*)p = __floats2half2_rn(a, b); }

// ---------------- fp16 GEMM: C[M,N] = A[M,K] @ B[K,N] + bias ----------------
// A half K-major; B half row-major [K][N]. M,N mult of 128, K mult of 32.
// 4-stage cp.async pipeline, 16 KB/stage dynamic smem.
template<bool GELU, typename OT>
__global__ void __launch_bounds__(256, 2)
gemmh(const __half* __restrict__ A, const __half* __restrict__ B,
      const float* __restrict__ bias, OT* __restrict__ C,
      int M, int N, int K)
{
    extern __shared__ __align__(16) unsigned char smem[];
    const int tid = threadIdx.x, lane = tid & 31, warp = tid >> 5;
    const int wm = warp & 1, wn = warp >> 1;       // warp tile 64x32
    const int rr = lane >> 2, cl = lane & 3;
    const int m0 = blockIdx.y * 128, n0 = blockIdx.x * 128;
    const __half* Arow = A + (size_t)m0 * K;
    const __half* Bcol = B + n0;
    const uint32_t sbase = smem_u32(smem);
    const int T = K >> 5;

    float acc[4][4][4];
    #pragma unroll
    for (int mt = 0; mt < 4; mt++)
        #pragma unroll
        for (int nt = 0; nt < 4; nt++)
            #pragma unroll
            for (int q = 0; q < 4; q++) acc[mt][nt][q] = 0.f;

    auto stage = [&](int t) {
        if (t < T) {
            const uint32_t sb = sbase + (t & 3) * 16384;
            const int k0 = t << 5;
            #pragma unroll
            for (int q = 0; q < 2; q++) {
                int ch = q * 256 + tid;                 // 0..511
                int row = ch >> 2, u = ch & 3;
                uint32_t off = row * 64 + ((u ^ ((row >> 1) & 3)) << 4);
                cpa16(sb + off, Arow + (size_t)row * K + k0 + u * 8);
            }
            #pragma unroll
            for (int q = 0; q < 2; q++) {
                int ch = q * 256 + tid;
                int k = ch >> 4, u = ch & 15;
                uint32_t off = k * 256 + ((u ^ (k & 7)) << 4);
                cpa16(sb + 8192 + off, Bcol + (size_t)(k0 + k) * N + u * 8);
            }
        }
        CPA_COMMIT();      // always commit (empty group past the end)
    };

    stage(0); stage(1); stage(2);
    for (int t = 0; t < T; t++) {
        asm volatile("cp.async.wait_group 2;" ::: "memory");
        __syncthreads();
        stage(t + 3);      // overwrites slot t-1 (safe: sync above)
        const uint32_t sA = sbase + (t & 3) * 16384;
        const uint32_t sB = sA + 8192;

        #pragma unroll
        for (int kk = 0; kk < 2; kk++) {
            const int u0 = kk * 2;
            uint32_t af[4][4], bf[4][2];
            #pragma unroll
            for (int mt = 0; mt < 4; mt++) {
                const int tr = wm * 64 + mt * 16;
                int row = tr + ((lane >> 3) & 1) * 8 + (lane & 7);
                int unit = u0 + (lane >> 4);
                uint32_t addr = sA + row * 64 + ((unit ^ ((row >> 1) & 3)) << 4);
                asm volatile("ldmatrix.sync.aligned.m8n8.x4.shared.b16 {%0,%1,%2,%3}, [%4];"
                             : "=r"(af[mt][0]), "=r"(af[mt][1]), "=r"(af[mt][2]), "=r"(af[mt][3])
                             : "r"(addr));
            }
            #pragma unroll
            for (int nt = 0; nt < 4; nt++) {
                int rowk = kk * 16 + (lane & 15);
                uint32_t addr = sB + rowk * 256 + (((wn * 4 + nt) ^ (rowk & 7)) << 4);
                asm volatile("ldmatrix.sync.aligned.m8n8.x2.trans.shared.b16 {%0,%1}, [%2];"
                             : "=r"(bf[nt][0]), "=r"(bf[nt][1]) : "r"(addr));
            }
            #pragma unroll
            for (int mt = 0; mt < 4; mt++)
                #pragma unroll
                for (int nt = 0; nt < 4; nt++)
                    mma_f16(acc[mt][nt], af[mt], bf[nt]);
        }
        __syncthreads();
    }

    #pragma unroll
    for (int mt = 0; mt < 4; mt++) {
        #pragma unroll
        for (int nt = 0; nt < 4; nt++) {
            int r  = m0 + wm * 64 + mt * 16 + rr;
            int cc = n0 + wn * 32 + nt * 8 + 2 * cl;
            float b0 = bias ? bias[cc]     : 0.f;
            float b1 = bias ? bias[cc + 1] : 0.f;
            float v0 = acc[mt][nt][0] + b0;
            float v1 = acc[mt][nt][1] + b1;
            float v2 = acc[mt][nt][2] + b0;
            float v3 = acc[mt][nt][3] + b1;
            if (GELU) {
                v0 = 0.5f * v0 * (1.f + erff(v0 * 0.70710678118654752f));
                v1 = 0.5f * v1 * (1.f + erff(v1 * 0.70710678118654752f));
                v2 = 0.5f * v2 * (1.f + erff(v2 * 0.70710678118654752f));
                v3 = 0.5f * v3 * (1.f + erff(v3 * 0.70710678118654752f));
            }
            st2(C + (size_t)r * N + cc,       v0, v1);
            st2(C + (size_t)(r + 8) * N + cc, v2, v3);
        }
    }
}

// ---------------- prep kernels ----------------
__global__ void cvth_k(const float* __restrict__ src, __half* __restrict__ dst)
{
    int i = (blockIdx.x * 256 + threadIdx.x) * 4;
    float4 v = *(const float4*)(src + i);
    *(__half2*)(dst + i)     = __floats2half2_rn(v.x, v.y);
    *(__half2*)(dst + i + 2) = __floats2half2_rn(v.z, v.w);
}

__global__ void wcat_k(const float* __restrict__ v_w, const float* __restrict__ v_b,
                       const float* __restrict__ qmod_w, const float* __restrict__ qmod_b,
                       const float* __restrict__ kmod_w, const float* __restrict__ kmod_b,
                       const float* __restrict__ cq_w,   const float* __restrict__ ck_w,
                       __half* __restrict__ wcat, float* __restrict__ bcat)
{
    int idx = blockIdx.x * 256 + threadIdx.x;          // over 1024*1408
    int k = idx / VPW, n = idx - k * VPW;
    float v = 0.f;
    if      (n < 1024) v = v_w[k*1024 + n];
    else {
        int c = n - 1024;
        if      (c < 16)  v = qmod_w[k*Hh + c];
        else if (c < 32)  v = kmod_w[k*Hh + (c - 16)];
        else if (c < 160) v = cq_w[k*(Hh*CRc) + (c - 32)];
        else if (c < 288) v = ck_w[k*(Hh*CRc) + (c - 160)];
    }
    wcat[idx] = __float2half_rn(v);
    if (idx < VPW) {
        float bv = 0.f;
        if (idx < 1024) bv = v_b[idx];
        else { int p = idx - 1024; if (p < 16) bv = qmod_b[p]; else if (p < 32) bv = kmod_b[p - 16]; }
        bcat[idx] = bv;
    }
}

// ---------------- pooled mean over S ----------------
__global__ void pool1_k(const float* __restrict__ x, float* __restrict__ pp)
{
    int idx = blockIdx.x * 256 + threadIdx.x;
    int sl  = blockIdx.y;                           // 0..63
    int b = idx >> 10, d = idx & 1023;
    const float* xp = x + (size_t)(b*Ss + sl*16)*Dd + d;
    float s0=0,s1=0;
    #pragma unroll
    for (int q = 0; q < 16; q += 2) {
        s0 += xp[(size_t)(q+0)*Dd];
        s1 += xp[(size_t)(q+1)*Dd];
    }
    pp[sl*2048 + idx] = s0+s1;
}

__global__ void pool2_k(const float* __restrict__ pp, float* __restrict__ pooled)
{
    int idx = blockIdx.x * 256 + threadIdx.x;
    float s = 0.f;
    #pragma unroll
    for (int q = 0; q < 64; q++) s += pp[q*2048 + idx];
    pooled[idx] = s * (1.f/Ss);
}

// ---------------- gating ----------------
__global__ void __launch_bounds__(256) gating_k(const float* __restrict__ pooled,
    const float* __restrict__ gate_w, const float* __restrict__ gate_b,
    const float* __restrict__ mod_w,  const float* __restrict__ mod_b,
    const float* __restrict__ mod_basis, float* __restrict__ wts)
{
    int blk = blockIdx.x;
    int b = blk / Hh, h = blk % Hh;
    int tid = threadIdx.x, warp = tid >> 5, lane = tid & 31;
    __shared__ float ps[Dd];
    __shared__ float outs[24];
    __shared__ float gls[MMm];
    for (int q = tid; q < Dd; q += 256) ps[q] = pooled[b*Dd + q];
    __syncthreads();
    for (int o = warp; o < 24; o += 8) {
        const float* wcol; int stride; float bias;
        if (o < 16) { wcol = gate_w + h*MMm + o;      stride = Hh*MMm; bias = gate_b[h*MMm + o]; }
        else        { int r = o-16; wcol = mod_w + h*RMm + r; stride = Hh*RMm; bias = mod_b[h*RMm + r]; }
        float s = 0.f;
        for (int dI = lane; dI < Dd; dI += 32) s += ps[dI] * wcol[(size_t)dI * stride];
        #pragma unroll
        for (int off = 16; off; off >>= 1) s += __shfl_xor_sync(0xffffffffu, s, off);
        if (lane == 0) outs[o] = s + bias;
    }
    __syncthreads();
    if (tid < MMm) {
        float gl = outs[tid];
        #pragma unroll
        for (int r = 0; r < RMm; r++) gl += outs[16 + r] * mod_basis[(r*Hh + h)*MMm + tid];
        gls[tid] = gl;
    }
    __syncthreads();
    if (tid == 0) {
        float mx = -1e30f;
        for (int m = 0; m < MMm; m++) mx = fmaxf(mx, gls[m]);
        float e[MMm], sm = 0.f;
        for (int m = 0; m < MMm; m++) { e[m] = expf(gls[m] - mx); sm += e[m]; }
        float inv = 1.f / sm;
        for (int m = 0; m < MMm; m++) wts[(b*Hh + h)*MMm + m] = e[m] * inv;
    }
}

// ---------------- wave mask -> causal Toeplitz row ----------------
__global__ void __launch_bounds__(256) wave_k(const float* __restrict__ wts,
    const float* __restrict__ freqs, const float* __restrict__ amps,
    const float* __restrict__ phases, float* __restrict__ ckr)
{
    int b = blockIdx.z, h = blockIdx.y;
    int d = blockIdx.x * 256 + threadIdx.x;
    __shared__ float fs[MMm*WWw*2], as_[MMm*WWw], ph_[MMm*WWw], ws[MMm];
    int t = threadIdx.x;
    fs[t] = freqs[h*MMm*WWw*2 + t];
    if (t < MMm*WWw) { as_[t] = amps[h*MMm*WWw + t]; ph_[t] = phases[h*MMm*WWw + t]; }
    if (t < MMm) ws[t] = wts[(b*Hh + h)*MMm + t];
    __syncthreads();
    float p1 = d * (1.f/Ss);
    float p2 = (d == 0) ? 0.f : sqrtf((float)d + 1e-6f) * 0.03125f;
    float kern = 0.f;
    #pragma unroll
    for (int m = 0; m < MMm; m++) {
        float acc = 0.f;
        #pragma unroll
        for (int w = 0; w < WWw; w++) {
            int iw = m*WWw + w;
            acc += as_[iw] * sinf(fs[iw*2+0]*p1 + fs[iw*2+1]*p2 + ph_[iw]);
        }
        kern += ws[m] * acc;
    }
    float dens = 1.f / (1.f + expf(-6.f * kern));
    float win  = expf(-(float)d * (float)d * (1.f/131072.f));
    ckr[(b*Hh + h)*Ss + d] = 3.f * dens * win;
}

// ---------------- flash attention, tensor-core PV, 128 queries/CTA ----------------
__global__ void __launch_bounds__(256) attn_k(const __half* __restrict__ vp,
    const float* __restrict__ ckr, __half* __restrict__ ctx)
{
    const int b = blockIdx.z, h = blockIdx.y;
    const int qb = (gridDim.x - 1 - blockIdx.x) * 128;     // big tiles first
    const int tid = threadIdx.x, warp = tid >> 5, lane = tid & 31;
    const int g = lane >> 2, c2 = (lane & 3) * 2;

    __shared__ float  ck_s[Ss];
    __shared__ __align__(16) __half vts[64 * 68];   // V^T: [d][j], stride 68
    __shared__ __align__(16) __half kcs[64 * 18];   // kc': [j][16], stride 18

    for (int o = tid; o < Ss; o += 256) ck_s[o] = ckr[(b*Hh + h)*Ss + o];

    const __half* vpB = vp + (size_t)(b*Ss) * VPW;
    const float cmix = 0.0530330085889911f;

    const int i_lo = qb + warp*16 + g, i_hi = i_lo + 8;
    uint32_t aq[4];
    {
        float qlo0 = cmix * __half2float(vpB[(size_t)i_lo*VPW + 1056 + h*CRc + c2]);
        float qlo1 = cmix * __half2float(vpB[(size_t)i_lo*VPW + 1056 + h*CRc + c2 + 1]);
        float qhi0 = cmix * __half2float(vpB[(size_t)i_hi*VPW + 1056 + h*CRc + c2]);
        float qhi1 = cmix * __half2float(vpB[(size_t)i_hi*VPW + 1056 + h*CRc + c2 + 1]);
        aq[0] = h2u(qlo0, qlo1);
        aq[1] = h2u(qhi0, qhi1);
        if ((lane & 3) == 0) {
            aq[2] = h2u(1.f, __half2float(vpB[(size_t)i_lo*VPW + 1024 + h]));
            aq[3] = h2u(1.f, __half2float(vpB[(size_t)i_hi*VPW + 1024 + h]));
        } else { aq[2] = 0; aq[3] = 0; }
    }

    float m_lo = -1e30f, m_hi = -1e30f, l_lo = 0.f, l_hi = 0.f;
    float o_[8][4];
    #pragma unroll
    for (int nt = 0; nt < 8; nt++)
        #pragma unroll
        for (int q = 0; q < 4; q++) o_[nt][q] = 0.f;

    const int iwmax = qb + warp*16 + 15;

    for (int jb = 0; jb <= qb + 64; jb += 64) {
        __syncthreads();
        if (tid < 128) {
            int j = tid >> 1, sub = tid & 1;
            uint32_t* dst = (uint32_t*)((char*)kcs + j*36 + sub*16);
            if (sub == 0) {
                const __half* kc = vpB + (size_t)(jb + j)*VPW + 1184 + h*CRc;
                dst[0] = *(const uint32_t*)(kc);
                dst[1] = *(const uint32_t*)(kc + 2);
                dst[2] = *(const uint32_t*)(kc + 4);
                dst[3] = *(const uint32_t*)(kc + 6);
            } else {
                float km = __half2float(vpB[(size_t)(jb + j)*VPW + 1040 + h]);
                dst[0] = h2u(km, 1.f); dst[1] = 0; dst[2] = 0; dst[3] = 0;
            }
        }
        #pragma unroll 4
        for (int it = 0; it < 16; it++) {
            int idx = it * 256 + tid;
            int j = idx >> 6, d = idx & 63;
            vts[d*68 + j] = vpB[(size_t)(jb + j)*VPW + h*HDd + d];
        }
        __syncthreads();

        if (jb <= iwmax) {
            float s[8][4];
            #pragma unroll
            for (int nt = 0; nt < 8; nt++) {
                s[nt][0] = s[nt][1] = s[nt][2] = s[nt][3] = 0.f;
                uint32_t kb[2];
                const char* base = (const char*)kcs + (nt*8 + g)*36 + (lane & 3)*4;
                kb[0] = *(const uint32_t*)(base);
                kb[1] = *(const uint32_t*)(base + 16);
                mma_f16(s[nt], aq, kb);
            }
            const int irl = i_lo - jb, irh = irl + 8;
            const bool mlo = (irl < 63), mhi = (irh < 63);
            #pragma unroll
            for (int nt = 0; nt < 8; nt++) {
                int j0 = nt*8 + c2;
                if (!mlo) {
                    s[nt][0] += ck_s[irl - j0];
                    s[nt][1] += ck_s[irl - j0 - 1];
                } else {
                    s[nt][0] = (j0     <= irl) ? s[nt][0] + ck_s[irl - j0]     : -1e30f;
                    s[nt][1] = (j0 + 1 <= irl) ? s[nt][1] + ck_s[irl - j0 - 1] : -1e30f;
                }
                if (!mhi) {
                    s[nt][2] += ck_s[irh - j0];
                    s[nt][3] += ck_s[irh - j0 - 1];
                } else {
                    s[nt][2] = (j0     <= irh) ? s[nt][2] + ck_s[irh - j0]     : -1e30f;
                    s[nt][3] = (j0 + 1 <= irh) ? s[nt][3] + ck_s[irh - j0 - 1] : -1e30f;
                }
            }
            float mx_lo = -1e30f, mx_hi = -1e30f;
            #pragma unroll
            for (int nt = 0; nt < 8; nt++) {
                mx_lo = fmaxf(mx_lo, fmaxf(s[nt][0], s[nt][1]));
                mx_hi = fmaxf(mx_hi, fmaxf(s[nt][2], s[nt][3]));
            }
            mx_lo = fmaxf(mx_lo, __shfl_xor_sync(0xffffffffu, mx_lo, 1));
            mx_lo = fmaxf(mx_lo, __shfl_xor_sync(0xffffffffu, mx_lo, 2));
            mx_hi = fmaxf(mx_hi, __shfl_xor_sync(0xffffffffu, mx_hi, 1));
            mx_hi = fmaxf(mx_hi, __shfl_xor_sync(0xffffffffu, mx_hi, 2));
            float mn_lo = fmaxf(m_lo, mx_lo), mn_hi = fmaxf(m_hi, mx_hi);
            float sc_lo = __expf(m_lo - mn_lo), sc_hi = __expf(m_hi - mn_hi);
            float p[8][4], sum_lo = 0.f, sum_hi = 0.f;
            #pragma unroll
            for (int nt = 0; nt < 8; nt++) {
                p[nt][0] = __expf(s[nt][0] - mn_lo);
                p[nt][1] = __expf(s[nt][1] - mn_lo);
                p[nt][2] = __expf(s[nt][2] - mn_hi);
                p[nt][3] = __expf(s[nt][3] - mn_hi);
                sum_lo += p[nt][0] + p[nt][1];
                sum_hi += p[nt][2] + p[nt][3];
            }
            sum_lo += __shfl_xor_sync(0xffffffffu, sum_lo, 1);
            sum_lo += __shfl_xor_sync(0xffffffffu, sum_lo, 2);
            sum_hi += __shfl_xor_sync(0xffffffffu, sum_hi, 1);
            sum_hi += __shfl_xor_sync(0xffffffffu, sum_hi, 2);
            l_lo = l_lo * sc_lo + sum_lo;  m_lo = mn_lo;
            l_hi = l_hi * sc_hi + sum_hi;  m_hi = mn_hi;
            #pragma unroll
            for (int nt = 0; nt < 8; nt++) {
                o_[nt][0] *= sc_lo; o_[nt][1] *= sc_lo;
                o_[nt][2] *= sc_hi; o_[nt][3] *= sc_hi;
            }
            #pragma unroll
            for (int kt = 0; kt < 4; kt++) {
                uint32_t pa[4];
                pa[0] = h2u(p[2*kt][0],   p[2*kt][1]);
                pa[1] = h2u(p[2*kt][2],   p[2*kt][3]);
                pa[2] = h2u(p[2*kt+1][0], p[2*kt+1][1]);
                pa[3] = h2u(p[2*kt+1][2], p[2*kt+1][3]);
                #pragma unroll
                for (int nt = 0; nt < 8; nt++) {
                    uint32_t vb[2];
                    const char* base = (const char*)vts + ((nt*8 + g)*68 + kt*16 + c2)*2;
                    vb[0] = *(const uint32_t*)(base);
                    vb[1] = *(const uint32_t*)(base + 16);
                    mma_f16(o_[nt], pa, vb);
                }
            }
        }
    }

    float inv_lo = 1.f / l_lo, inv_hi = 1.f / l_hi;
    #pragma unroll
    for (int nt = 0; nt < 8; nt++) {
        __half2* plo = (__half2*)(ctx + (size_t)(b*Ss + i_lo)*Dd + h*HDd + nt*8 + c2);
        __half2* phi = (__half2*)(ctx + (size_t)(b*Ss + i_hi)*Dd + h*HDd + nt*8 + c2);
        *plo = __floats2half2_rn(o_[nt][0]*inv_lo, o_[nt][1]*inv_lo);
        *phi = __floats2half2_rn(o_[nt][2]*inv_hi, o_[nt][3]*inv_hi);
    }
}

// ---------------- fused residual + LayerNorm ----------------
__global__ void __launch_bounds__(256) ln_k(const float* __restrict__ a,
    const float* __restrict__ r, const float* __restrict__ g,
    const float* __restrict__ bta, float* __restrict__ out, __half* __restrict__ out2)
{
    int row = blockIdx.x;
    size_t base = (size_t)row * Dd;
    int tid = threadIdx.x;
    float vals[4], s = 0.f, s2 = 0.f;
    #pragma unroll
    for (int q = 0; q < 4; q++) {
        int idx = tid + q*256;
        float xv = a[base + idx] + r[base + idx];
        vals[q] = xv; s += xv; s2 += xv*xv;
    }
    __shared__ float red[64];
    #pragma unroll
    for (int o = 16; o; o >>= 1) {
        s  += __shfl_xor_sync(0xffffffffu, s,  o);
        s2 += __shfl_xor_sync(0xffffffffu, s2, o);
    }
    int warp = tid >> 5, lane = tid & 31;
    if (lane == 0) { red[warp] = s; red[32 + warp] = s2; }
    __syncthreads();
    if (warp == 0) {
        float a1 = (lane < 8) ? red[lane] : 0.f;
        float a2 = (lane < 8) ? red[32 + lane] : 0.f;
        #pragma unroll
        for (int o = 4; o; o >>= 1) {
            a1 += __shfl_xor_sync(0xffffffffu, a1, o);
            a2 += __shfl_xor_sync(0xffffffffu, a2, o);
        }
        if (lane == 0) { red[0] = a1; red[1] = a2; }
    }
    __syncthreads();
    float mean = red[0] * (1.f/Dd);
    float var  = red[1] * (1.f/Dd) - mean*mean;
    float rstd = rsqrtf(var + 1e-5f);
    #pragma unroll
    for (int q = 0; q < 4; q++) {
        int idx = tid + q*256;
        float o = (vals[q] - mean) * rstd * g[idx] + bta[idx];
        out[base + idx] = o;
        if (out2) out2[base + idx] = __float2half_rn(o);
    }
}

// ---------------- launch ----------------
extern "C" void kernel_launch(void* const* d_in, const int* in_sizes, int n_in,
                              void* d_out, int out_size)
{
    const float* x      = (const float*)d_in[0];
    const float* v_w    = (const float*)d_in[1];
    const float* v_b    = (const float*)d_in[2];
    const float* out_w  = (const float*)d_in[3];
    const float* out_b  = (const float*)d_in[4];
    const float* qmod_w = (const float*)d_in[5];
    const float* qmod_b = (const float*)d_in[6];
    const float* kmod_w = (const float*)d_in[7];
    const float* kmod_b = (const float*)d_in[8];
    const float* gate_w = (const float*)d_in[9];
    const float* gate_b = (const float*)d_in[10];
    const float* mod_w  = (const float*)d_in[11];
    const float* mod_b  = (const float*)d_in[12];
    const float* mod_basis = (const float*)d_in[13];
    const float* freqs  = (const float*)d_in[14];
    const float* amps   = (const float*)d_in[15];
    const float* phases = (const float*)d_in[16];
    const float* cq_w   = (const float*)d_in[17];
    const float* ck_w   = (const float*)d_in[18];
    const float* ffn_w1 = (const float*)d_in[19];
    const float* ffn_b1 = (const float*)d_in[20];
    const float* ffn_w2 = (const float*)d_in[21];
    const float* ffn_b2 = (const float*)d_in[22];
    const float* ln1_g  = (const float*)d_in[23];
    const float* ln1_b  = (const float*)d_in[24];
    const float* ln2_g  = (const float*)d_in[25];
    const float* ln2_b  = (const float*)d_in[26];
    float* out = (float*)d_out;

    __half *pxh, *pwcat, *pvph, *powh, *pw1h, *pw2h, *pctxh, *phch, *pffnh;
    float *pbcat, *ppp, *ppool, *pwts, *pck, *pao, *ph, *pf2;
    cudaGetSymbolAddress((void**)&pxh,  g_xh);
    cudaGetSymbolAddress((void**)&pwcat,g_wcat);
    cudaGetSymbolAddress((void**)&pbcat,g_bcat);
    cudaGetSymbolAddress((void**)&pvph, g_vph);
    cudaGetSymbolAddress((void**)&powh, g_owh);
    cudaGetSymbolAddress((void**)&pw1h, g_w1h);
    cudaGetSymbolAddress((void**)&pw2h, g_w2h);
    cudaGetSymbolAddress((void**)&pctxh,g_ctxh);
    cudaGetSymbolAddress((void**)&phch, g_hch);
    cudaGetSymbolAddress((void**)&pffnh,g_ffnh);
    cudaGetSymbolAddress((void**)&ppp,  g_pp);
    cudaGetSymbolAddress((void**)&ppool,g_pool);
    cudaGetSymbolAddress((void**)&pwts, g_wts);
    cudaGetSymbolAddress((void**)&pck,  g_ckr);
    cudaGetSymbolAddress((void**)&pao,  g_ao);
    cudaGetSymbolAddress((void**)&ph,   g_h);
    cudaGetSymbolAddress((void**)&pf2,  g_f2);

    cudaFuncSetAttribute(gemmh<false,__half>, cudaFuncAttributeMaxDynamicSharedMemorySize, 65536);
    cudaFuncSetAttribute(gemmh<false,float>,  cudaFuncAttributeMaxDynamicSharedMemorySize, 65536);
    cudaFuncSetAttribute(gemmh<true,__half>,  cudaFuncAttributeMaxDynamicSharedMemorySize, 65536);

    // prep
    cvth_k<<<(ROWS*Dd)/1024, 256>>>(x, pxh);
    wcat_k<<<(Dd*VPW)/256, 256>>>(v_w, v_b, qmod_w, qmod_b, kmod_w, kmod_b, cq_w, ck_w, pwcat, pbcat);
    cvth_k<<<(Dd*Dd)/1024, 256>>>(out_w, powh);
    cvth_k<<<(Dd*FFD)/1024, 256>>>(ffn_w1, pw1h);
    cvth_k<<<(FFD*Dd)/1024, 256>>>(ffn_w2, pw2h);

    // fused v + proj GEMM (half output)
    gemmh<false,__half><<<dim3(VPW/128, ROWS/128), 256, 65536>>>(pxh, pwcat, pbcat, pvph, ROWS, VPW, Dd);

    // gating path
    pool1_k<<<dim3(8,64), 256>>>(x, ppp);
    pool2_k<<<8, 256>>>(ppp, ppool);
    gating_k<<<Bb*Hh, 256>>>(ppool, gate_w, gate_b, mod_w, mod_b, mod_basis, pwts);
    wave_k<<<dim3(Ss/256, Hh, Bb), 256>>>(pwts, freqs, amps, phases, pck);

    // attention
    attn_k<<<dim3(Ss/128, Hh, Bb), 256>>>(pvph, pck, pctxh);
    gemmh<false,float><<<dim3(Dd/128, ROWS/128), 256, 65536>>>(pctxh, powh, out_b, pao, ROWS, Dd, Dd);

    // LN1 + FFN + LN2
    ln_k<<<ROWS, 256>>>(x, pao, ln1_g, ln1_b, ph, phch);
    gemmh<true,__half><<<dim3(FFD/128, ROWS/128), 256, 65536>>>(phch,  pw1h, ffn_b1, pffnh, ROWS, FFD, Dd);
    gemmh<false,float><<<dim3(Dd/128, ROWS/128), 256, 65536>>>(pffnh, pw2h, ffn_b2, pf2,  ROWS, Dd, FFD);
    ln_k<<<ROWS, 256>>>(ph, pf2, ln2_g, ln2_b, out, nullptr);
}